// round 4
// baseline (speedup 1.0000x reference)
#include <cuda_runtime.h>
#include <math.h>
#include <stdint.h>

#define NB 16
#define NN 2048
#define NM 64
#define NR 4
#define NH 512
#define NCIN 320
#define NCOUT 535
#define NKEYS 5
#define FEPS 1e-8f

// ---- output layout (tuple flattened in reference return order) ----
#define OUT_OUTPUT 0
#define OUT_MEM    ((size_t)(NB*64))
#define OUT_LINK   (OUT_MEM + (size_t)NB*NN*NM)
#define OUT_P      (OUT_LINK + (size_t)NB*NN*NN)
#define OUT_USAGE  (OUT_P + (size_t)NB*NN)
#define OUT_READW  (OUT_USAGE + (size_t)NB*NN)

// ---- scratch (static device globals; no allocation) ----
__device__ float g_gates[NB*4*NH];
__device__ float g_h[NB*NH];
__device__ float g_ctrl[NB*NCOUT];
__device__ float g_keys[NB*NKEYS*NM];    // 4 read keys + write key (post-sigmoid)
__device__ float g_betas[NB*NKEYS];
__device__ float g_knorm[NB*NKEYS];
__device__ float g_free[NB*NR];
__device__ float g_erase[NB*NM];
__device__ float g_wvec[NB*NM];
__device__ float g_agate[NB];
__device__ float g_wgate[NB];
__device__ float g_modes[NB*NR*3];
__device__ float g_taskout[NB*64];
__device__ float g_cw[NB*NKEYS*NN];      // beta*sim logits -> content weights
__device__ float g_alloc[NB*NN];
__device__ float g_ww[NB*NN];
__device__ float g_fwd[NB*NR*NN];
__device__ float g_bwd[NB*NR*NN];

__device__ __forceinline__ float sigm(float x){ return 1.0f/(1.0f+expf(-x)); }
__device__ __forceinline__ float softplusf(float x){ return fmaxf(x,0.0f) + log1pf(expf(-fabsf(x))); }

// ================= K1: LSTM gates  gates = x@Wih^T + h@Whh^T + b =================
__global__ void k_gates(const float* __restrict__ task, const float* __restrict__ prev_reads,
                        const float* __restrict__ h_prev, const float* __restrict__ W_ih,
                        const float* __restrict__ W_hh, const float* __restrict__ b_lstm){
    int gid = blockIdx.x*blockDim.x + threadIdx.x;   // 32768
    int b = gid & (NB-1);
    int g = gid >> 4;
    if (g >= 4*NH) return;
    float acc = b_lstm[g];
    const float4* wi = (const float4*)(W_ih + (size_t)g*NCIN);
    const float4* t4 = (const float4*)(task + b*64);
    const float4* r4 = (const float4*)(prev_reads + b*(NR*NM));
    #pragma unroll 4
    for (int k = 0; k < 16; k++){
        float4 w = wi[k]; float4 x = t4[k];
        acc += w.x*x.x + w.y*x.y + w.z*x.z + w.w*x.w;
    }
    #pragma unroll 4
    for (int k = 0; k < 64; k++){
        float4 w = wi[16+k]; float4 x = r4[k];
        acc += w.x*x.x + w.y*x.y + w.z*x.z + w.w*x.w;
    }
    const float4* wh = (const float4*)(W_hh + (size_t)g*NH);
    const float4* h4 = (const float4*)(h_prev + b*NH);
    #pragma unroll 4
    for (int k = 0; k < 128; k++){
        float4 w = wh[k]; float4 x = h4[k];
        acc += w.x*x.x + w.y*x.y + w.z*x.z + w.w*x.w;
    }
    g_gates[b*(4*NH) + g] = acc;
}

// ================= K2: LSTM cell =================
__global__ void k_lstm(const float* __restrict__ c_prev){
    int gid = blockIdx.x*blockDim.x + threadIdx.x;   // 8192
    if (gid >= NB*NH) return;
    int b = gid >> 9;
    int k = gid & (NH-1);
    const float* gb = g_gates + b*(4*NH);
    float gi = gb[k], gf = gb[NH+k], gg = gb[2*NH+k], go = gb[3*NH+k];
    float c = sigm(gf)*c_prev[gid] + sigm(gi)*tanhf(gg);
    g_h[gid] = sigm(go)*tanhf(c);
}

// ================= K3: out = h @ W_out^T + b_out =================
__global__ void k_out(const float* __restrict__ W_out, const float* __restrict__ b_out){
    int gid = blockIdx.x*blockDim.x + threadIdx.x;
    if (gid >= NB*NCOUT) return;
    int b = gid & (NB-1);
    int o = gid >> 4;
    float acc = b_out[o];
    const float4* w4 = (const float4*)(W_out + (size_t)o*NH);
    const float4* h4 = (const float4*)(g_h + b*NH);
    #pragma unroll 4
    for (int k = 0; k < 128; k++){
        float4 w = w4[k]; float4 x = h4[k];
        acc += w.x*x.x + w.y*x.y + w.z*x.z + w.w*x.w;
    }
    g_ctrl[b*NCOUT + o] = acc;
}

// ================= K3b: parse controller outputs =================
__global__ void k_parse(){
    int tid = threadIdx.x;
    for (int idx = tid; idx < NB*NCOUT; idx += blockDim.x){
        int b = idx / NCOUT, c = idx % NCOUT;
        float v = g_ctrl[idx];
        if (c < 64)        g_taskout[b*64 + c] = sigm(v);
        else if (c < 320)  g_keys[b*NKEYS*NM + (c-64)] = sigm(v);            // read keys 0..3
        else if (c < 324)  g_betas[b*NKEYS + (c-320)] = 1.0f + softplusf(v);
        else if (c < 328)  g_free[b*NR + (c-324)] = sigm(v);
        else if (c < 392)  g_keys[b*NKEYS*NM + 4*NM + (c-328)] = sigm(v);    // write key
        else if (c == 392) g_betas[b*NKEYS + 4] = 1.0f + softplusf(v);
        else if (c < 457)  g_erase[b*NM + (c-393)] = sigm(v);
        else if (c < 521)  g_wvec[b*NM + (c-457)] = sigm(v);
        else if (c == 521) g_agate[b] = sigm(v);
        else if (c == 522) g_wgate[b] = sigm(v);
        else               g_modes[b*12 + (c-523)] = v;                      // raw logits
    }
    __syncthreads();
    if (tid < NB*NR){            // softmax over 3 read modes
        float* m = g_modes + tid*3;
        float a = m[0], bb = m[1], cc = m[2];
        float mx = fmaxf(a, fmaxf(bb, cc));
        float e0 = expf(a-mx), e1 = expf(bb-mx), e2 = expf(cc-mx);
        float s = e0+e1+e2;
        m[0]=e0/s; m[1]=e1/s; m[2]=e2/s;
    }
    if (tid < NB*NKEYS){         // key norms
        const float* kp = g_keys + tid*NM;
        float s = 0.0f;
        #pragma unroll 8
        for (int i = 0; i < NM; i++){ float x = kp[i]; s += x*x; }
        g_knorm[tid] = sqrtf(s);
    }
}

// ================= K4: cosine similarity logits (beta*sim) =================
__global__ void k_sim(const float* __restrict__ memory){
    __shared__ float keys_sh[NKEYS*NM];
    __shared__ float beta_sh[NKEYS], kn_sh[NKEYS];
    int b = blockIdx.x >> 5;
    int tile = blockIdx.x & 31;
    int tid = threadIdx.x;
    for (int i = tid; i < NKEYS*NM; i += blockDim.x) keys_sh[i] = g_keys[b*NKEYS*NM + i];
    if (tid < NKEYS){ beta_sh[tid] = g_betas[b*NKEYS+tid]; kn_sh[tid] = g_knorm[b*NKEYS+tid]; }
    __syncthreads();
    int warp = tid >> 5, lane = tid & 31;
    #pragma unroll
    for (int rr = 0; rr < 8; rr++){
        int n = tile*64 + warp*8 + rr;
        const float* mrow = memory + ((size_t)b*NN + n)*NM;
        float a0 = mrow[lane], a1 = mrow[lane+32];
        float nrm = a0*a0 + a1*a1;
        float d0 = a0*keys_sh[0*NM+lane] + a1*keys_sh[0*NM+32+lane];
        float d1 = a0*keys_sh[1*NM+lane] + a1*keys_sh[1*NM+32+lane];
        float d2 = a0*keys_sh[2*NM+lane] + a1*keys_sh[2*NM+32+lane];
        float d3 = a0*keys_sh[3*NM+lane] + a1*keys_sh[3*NM+32+lane];
        float d4 = a0*keys_sh[4*NM+lane] + a1*keys_sh[4*NM+32+lane];
        #pragma unroll
        for (int s = 16; s; s >>= 1){
            nrm += __shfl_xor_sync(0xffffffffu, nrm, s);
            d0  += __shfl_xor_sync(0xffffffffu, d0,  s);
            d1  += __shfl_xor_sync(0xffffffffu, d1,  s);
            d2  += __shfl_xor_sync(0xffffffffu, d2,  s);
            d3  += __shfl_xor_sync(0xffffffffu, d3,  s);
            d4  += __shfl_xor_sync(0xffffffffu, d4,  s);
        }
        if (lane == 0){
            float mn = sqrtf(nrm);
            float dd[5] = {d0,d1,d2,d3,d4};
            #pragma unroll
            for (int k = 0; k < 5; k++)
                g_cw[((size_t)b*NKEYS + k)*NN + n] = beta_sh[k]*dd[k]/(kn_sh[k]*mn + FEPS);
        }
    }
}

// ================= K5: softmax over N for each (b, key) row =================
__global__ void k_softmax(){
    __shared__ float buf[NN];
    __shared__ float red[256];
    int row = blockIdx.x;          // 80 rows
    float* p = g_cw + (size_t)row*NN;
    int tid = threadIdx.x;
    float mx = -1e30f;
    for (int i = tid; i < NN; i += 256){ float v = p[i]; buf[i] = v; mx = fmaxf(mx, v); }
    red[tid] = mx; __syncthreads();
    for (int s = 128; s; s >>= 1){ if (tid < s) red[tid] = fmaxf(red[tid], red[tid+s]); __syncthreads(); }
    mx = red[0]; __syncthreads();
    float sum = 0.0f;
    for (int i = tid; i < NN; i += 256){ float e = expf(buf[i]-mx); buf[i] = e; sum += e; }
    red[tid] = sum; __syncthreads();
    for (int s = 128; s; s >>= 1){ if (tid < s) red[tid] += red[tid+s]; __syncthreads(); }
    float inv = 1.0f/red[0];
    for (int i = tid; i < NN; i += 256) p[i] = buf[i]*inv;
}

// ================= K6: usage =================
__global__ void k_usage(const float* __restrict__ pu, const float* __restrict__ pww,
                        const float* __restrict__ prw, float* __restrict__ outU){
    int gid = blockIdx.x*blockDim.x + threadIdx.x;   // 32768
    if (gid >= NB*NN) return;
    int b = gid >> 11;
    int n = gid & (NN-1);
    float psi = 1.0f;
    #pragma unroll
    for (int r = 0; r < NR; r++)
        psi *= 1.0f - g_free[b*NR+r]*prw[((size_t)b*NR + r)*NN + n];
    float u = pu[gid], w = pww[gid];
    outU[gid] = (u + w - u*w)*psi;
}

// ================= K7: allocation weighting (stable sort + cumprod) =================
__global__ void k_alloc(const float* __restrict__ usage){
    __shared__ float sv[NN];
    __shared__ int   si[NN];
    __shared__ float cA[NN];
    __shared__ float cB[NN];
    int b = blockIdx.x, tid = threadIdx.x;   // 1024 threads
    for (int i = tid; i < NN; i += 1024){ sv[i] = usage[b*NN + i]; si[i] = i; }
    __syncthreads();
    // bitonic ascending, tie-break by index (== stable argsort)
    for (int k = 2; k <= NN; k <<= 1){
        for (int j = k >> 1; j > 0; j >>= 1){
            for (int i = tid; i < NN; i += 1024){
                int p = i ^ j;
                if (p > i){
                    float av = sv[i], bv = sv[p];
                    int ai = si[i], bi = si[p];
                    bool gt = (av > bv) || (av == bv && ai > bi);
                    bool up = ((i & k) == 0);
                    if (up == gt){ sv[i]=bv; sv[p]=av; si[i]=bi; si[p]=ai; }
                }
            }
            __syncthreads();
        }
    }
    // inclusive product scan (Hillis-Steele, ping-pong)
    for (int i = tid; i < NN; i += 1024) cA[i] = sv[i];
    __syncthreads();
    float* src = cA; float* dst = cB;
    for (int off = 1; off < NN; off <<= 1){
        for (int i = tid; i < NN; i += 1024) dst[i] = (i >= off) ? src[i]*src[i-off] : src[i];
        __syncthreads();
        float* t = src; src = dst; dst = t;
    }
    for (int i = tid; i < NN; i += 1024){
        float excl = (i == 0) ? 1.0f : src[i-1];
        g_alloc[b*NN + si[i]] = (1.0f - sv[i])*excl;
    }
}

// ================= K8: write weights + precedence =================
__global__ void k_writew(const float* __restrict__ prec, float* __restrict__ outP){
    __shared__ float red[256];
    int b = blockIdx.x, tid = threadIdx.x;
    float ag = g_agate[b], wg = g_wgate[b];
    const float* cww = g_cw + ((size_t)b*NKEYS + 4)*NN;
    float s = 0.0f;
    for (int n = tid; n < NN; n += 256){
        float ww = wg*(ag*g_alloc[b*NN+n] + (1.0f-ag)*cww[n]);
        g_ww[b*NN+n] = ww;
        s += ww;
    }
    red[tid] = s; __syncthreads();
    for (int st = 128; st; st >>= 1){ if (tid < st) red[tid] += red[tid+st]; __syncthreads(); }
    float oms = 1.0f - red[0];
    for (int n = tid; n < NN; n += 256)
        outP[b*NN+n] = oms*prec[b*NN+n] + g_ww[b*NN+n];
}

// ================= K9: memory erase/write update =================
__global__ void k_memupd(const float* __restrict__ memory, float* __restrict__ outM){
    int t = blockIdx.x*blockDim.x + threadIdx.x;   // 524288 float4s
    if (t >= NB*NN*NM/4) return;
    int m4 = t & 15;
    int n  = (t >> 4) & (NN-1);
    int b  = t >> 15;
    float ww = g_ww[b*NN + n];
    float4 mm = ((const float4*)memory)[t];
    float4 e4 = ((const float4*)g_erase)[b*16 + m4];
    float4 v4 = ((const float4*)g_wvec)[b*16 + m4];
    float4 o;
    o.x = mm.x*(1.0f - ww*e4.x) + ww*v4.x;
    o.y = mm.y*(1.0f - ww*e4.y) + ww*v4.y;
    o.z = mm.z*(1.0f - ww*e4.z) + ww*v4.z;
    o.w = mm.w*(1.0f - ww*e4.w) + ww*v4.w;
    ((float4*)outM)[t] = o;
}

// ================= K10: zero bwd accumulator =================
__global__ void k_zero(){
    int t = blockIdx.x*blockDim.x + threadIdx.x;
    if (t < NB*NR*NN) g_bwd[t] = 0.0f;
}

// ================= K11: fused link update + fwd/bwd einsums (ONE pass over L) ====
// Block = (batch, 64-row tile); 8 warps x 8 rows/warp. Warps sweep the 2048
// columns in 8 staggered 256-col phases (syncthreads between) so bwd partials
// accumulate in shared WITHOUT atomics. fwd accumulates in registers per row.
__global__ void __launch_bounds__(256, 2)
k_link(const float* __restrict__ L, const float* __restrict__ prw,
       const float* __restrict__ pnew, float* __restrict__ outL){
    extern __shared__ float sm[];
    float* w_sh   = sm;            // prev_read_weights[b]  (4*2048)
    float* bwd_sh = sm + 4*NN;     // bwd partials          (4*2048)
    float* p_sh   = sm + 8*NN;     // p_new[b]              (2048)
    float* wwc_sh = sm + 9*NN;     // write_w[b]            (2048)
    int b = blockIdx.x >> 5;
    int tile = blockIdx.x & 31;
    int rowbase = tile*64;
    int tid = threadIdx.x, warp = tid >> 5, lane = tid & 31;
    for (int i = tid; i < 4*NN; i += 256){ w_sh[i] = prw[(size_t)b*4*NN + i]; bwd_sh[i] = 0.0f; }
    for (int i = tid; i < NN; i += 256){ p_sh[i] = pnew[b*NN + i]; wwc_sh[i] = g_ww[b*NN + i]; }
    __syncthreads();

    int row0 = rowbase + warp*8;
    float wwr[8], wr0[8], wr1[8], wr2[8], wr3[8];
    #pragma unroll
    for (int rr = 0; rr < 8; rr++){
        wwr[rr] = wwc_sh[row0 + rr - rowbase + rowbase]; // == g_ww row weight
        wr0[rr] = w_sh[row0+rr];      wr1[rr] = w_sh[NN+row0+rr];
        wr2[rr] = w_sh[2*NN+row0+rr]; wr3[rr] = w_sh[3*NN+row0+rr];
    }
    // wwr from wwc_sh needs the global row index:
    #pragma unroll
    for (int rr = 0; rr < 8; rr++) wwr[rr] = wwc_sh[row0 + rr];

    float f0[8]={0},f1[8]={0},f2[8]={0},f3[8]={0};
    const float* Lb = L + (size_t)b*NN*NN;
    float* Ob = outL + (size_t)b*NN*NN;

    for (int s = 0; s < 8; s++){
        int chunk = ((warp + s) & 7)*256;
        #pragma unroll
        for (int c = 0; c < 8; c++){
            int j = chunk + c*32 + lane;
            float pj = p_sh[j];
            float aj = 1.0f - wwc_sh[j];
            float k0 = w_sh[j], k1 = w_sh[NN+j], k2 = w_sh[2*NN+j], k3 = w_sh[3*NN+j];
            float b0 = 0.f, b1 = 0.f, b2 = 0.f, b3 = 0.f;
            #pragma unroll
            for (int rr = 0; rr < 8; rr++){
                size_t off = (size_t)(row0+rr)*NN + j;
                float l = __ldg(Lb + off);
                float o = fmaf(aj - wwr[rr], l, wwr[rr]*pj);
                Ob[off] = (row0+rr == j) ? 0.0f : o;
                f0[rr] = fmaf(l, k0, f0[rr]);
                f1[rr] = fmaf(l, k1, f1[rr]);
                f2[rr] = fmaf(l, k2, f2[rr]);
                f3[rr] = fmaf(l, k3, f3[rr]);
                b0 = fmaf(wr0[rr], l, b0);
                b1 = fmaf(wr1[rr], l, b1);
                b2 = fmaf(wr2[rr], l, b2);
                b3 = fmaf(wr3[rr], l, b3);
            }
            bwd_sh[j]      += b0;
            bwd_sh[NN+j]   += b1;
            bwd_sh[2*NN+j] += b2;
            bwd_sh[3*NN+j] += b3;
        }
        __syncthreads();
    }

    // fwd: warp-reduce and write (block owns these rows exclusively)
    #pragma unroll
    for (int rr = 0; rr < 8; rr++){
        float v0 = f0[rr], v1 = f1[rr], v2 = f2[rr], v3 = f3[rr];
        #pragma unroll
        for (int st = 16; st; st >>= 1){
            v0 += __shfl_xor_sync(0xffffffffu, v0, st);
            v1 += __shfl_xor_sync(0xffffffffu, v1, st);
            v2 += __shfl_xor_sync(0xffffffffu, v2, st);
            v3 += __shfl_xor_sync(0xffffffffu, v3, st);
        }
        if (lane == 0){
            int n = row0 + rr;
            g_fwd[((size_t)b*4 + 0)*NN + n] = v0;
            g_fwd[((size_t)b*4 + 1)*NN + n] = v1;
            g_fwd[((size_t)b*4 + 2)*NN + n] = v2;
            g_fwd[((size_t)b*4 + 3)*NN + n] = v3;
        }
    }
    // flush bwd partials (32 row-tiles per batch -> global accumulate)
    for (int i = tid; i < 4*NN; i += 256)
        atomicAdd(&g_bwd[(size_t)b*4*NN + i], bwd_sh[i]);
}

// ================= K12: read weights combine + reads + final output =============
__global__ void k_read(const float* __restrict__ memory, const float* __restrict__ W_read,
                       const float* __restrict__ b_read, float* __restrict__ outRW,
                       float* __restrict__ outO){
    __shared__ float rw_sh[4*NN];       // 32KB
    __shared__ float reads_sh[NR*NM];   // 256 floats
    __shared__ float modes_sh[12];
    int b = blockIdx.x, tid = threadIdx.x;
    if (tid < 12) modes_sh[tid] = g_modes[b*12 + tid];
    if (tid < NR*NM) reads_sh[tid] = 0.0f;
    __syncthreads();
    for (int i = tid; i < 4*NN; i += 256){
        int r = i >> 11, n = i & (NN-1);
        float m0 = modes_sh[r*3+0], m1 = modes_sh[r*3+1], m2 = modes_sh[r*3+2];
        float rw = m0*g_bwd[((size_t)b*4 + r)*NN + n]
                 + m1*g_cw[((size_t)b*NKEYS + r)*NN + n]
                 + m2*g_fwd[((size_t)b*4 + r)*NN + n];
        rw_sh[i] = rw;
        outRW[(size_t)b*4*NN + i] = rw;
    }
    __syncthreads();
    int warp = tid >> 5, lane = tid & 31;
    float a00=0,a01=0,a10=0,a11=0,a20=0,a21=0,a30=0,a31=0;
    for (int n = warp; n < NN; n += 8){
        const float* mrow = memory + ((size_t)b*NN + n)*NM;
        float v0 = mrow[lane], v1 = mrow[lane+32];
        float r0 = rw_sh[n], r1 = rw_sh[NN+n], r2 = rw_sh[2*NN+n], r3 = rw_sh[3*NN+n];
        a00 = fmaf(r0, v0, a00); a01 = fmaf(r0, v1, a01);
        a10 = fmaf(r1, v0, a10); a11 = fmaf(r1, v1, a11);
        a20 = fmaf(r2, v0, a20); a21 = fmaf(r2, v1, a21);
        a30 = fmaf(r3, v0, a30); a31 = fmaf(r3, v1, a31);
    }
    atomicAdd(&reads_sh[0*NM + lane],      a00); atomicAdd(&reads_sh[0*NM + lane + 32], a01);
    atomicAdd(&reads_sh[1*NM + lane],      a10); atomicAdd(&reads_sh[1*NM + lane + 32], a11);
    atomicAdd(&reads_sh[2*NM + lane],      a20); atomicAdd(&reads_sh[2*NM + lane + 32], a21);
    atomicAdd(&reads_sh[3*NM + lane],      a30); atomicAdd(&reads_sh[3*NM + lane + 32], a31);
    __syncthreads();
    if (tid < 64){
        float acc = b_read[tid];
        #pragma unroll 8
        for (int k = 0; k < NR*NM; k++)
            acc += W_read[tid*(NR*NM) + k]*reads_sh[k];
        float ro = sigm(acc);
        outO[b*64 + tid] = sigm(ro + g_taskout[b*64 + tid]);
    }
}

// ================= launch =================
extern "C" void kernel_launch(void* const* d_in, const int* in_sizes, int n_in,
                              void* d_out, int out_size){
    const float* task       = (const float*)d_in[0];
    const float* memory     = (const float*)d_in[1];
    const float* L          = (const float*)d_in[2];
    const float* prev_reads = (const float*)d_in[3];
    const float* prw        = (const float*)d_in[4];
    const float* pu         = (const float*)d_in[5];
    const float* pww        = (const float*)d_in[6];
    const float* prec       = (const float*)d_in[7];
    const float* h_prev     = (const float*)d_in[8];
    const float* c_prev     = (const float*)d_in[9];
    const float* W_ih       = (const float*)d_in[10];
    const float* W_hh       = (const float*)d_in[11];
    const float* b_lstm     = (const float*)d_in[12];
    const float* W_out      = (const float*)d_in[13];
    const float* b_out      = (const float*)d_in[14];
    const float* W_read     = (const float*)d_in[15];
    const float* b_read     = (const float*)d_in[16];

    float* out   = (float*)d_out;
    float* outO  = out + OUT_OUTPUT;
    float* outM  = out + OUT_MEM;
    float* outL  = out + OUT_LINK;
    float* outP  = out + OUT_P;
    float* outU  = out + OUT_USAGE;
    float* outRW = out + OUT_READW;

    const int LINK_SMEM = (4*NN + 4*NN + NN + NN) * 4;  // 81920 B
    cudaFuncSetAttribute(k_link, cudaFuncAttributeMaxDynamicSharedMemorySize, LINK_SMEM);

    k_gates  <<<128, 256>>>(task, prev_reads, h_prev, W_ih, W_hh, b_lstm);
    k_lstm   <<<32, 256>>>(c_prev);
    k_out    <<<(NB*NCOUT + 255)/256, 256>>>(W_out, b_out);
    k_parse  <<<1, 512>>>();
    k_sim    <<<512, 256>>>(memory);
    k_softmax<<<NB*NKEYS, 256>>>();
    k_usage  <<<128, 256>>>(pu, pww, prw, outU);
    k_alloc  <<<NB, 1024>>>(outU);
    k_writew <<<NB, 256>>>(prec, outP);
    k_memupd <<<2048, 256>>>(memory, outM);
    k_zero   <<<512, 256>>>();
    k_link   <<<512, 256, LINK_SMEM>>>(L, prw, outP, outL);
    k_read   <<<NB, 256>>>(memory, W_read, b_read, outRW, outO);
}

// round 5
// speedup vs baseline: 1.0763x; 1.0763x over previous
#include <cuda_runtime.h>
#include <math.h>
#include <stdint.h>

#define NB 16
#define NN 2048
#define NM 64
#define NR 4
#define NH 512
#define NCIN 320
#define NCOUT 535
#define NKEYS 5
#define FEPS 1e-8f

// ---- output layout (tuple flattened in reference return order) ----
#define OUT_OUTPUT 0
#define OUT_MEM    ((size_t)(NB*64))
#define OUT_LINK   (OUT_MEM + (size_t)NB*NN*NM)
#define OUT_P      (OUT_LINK + (size_t)NB*NN*NN)
#define OUT_USAGE  (OUT_P + (size_t)NB*NN)
#define OUT_READW  (OUT_USAGE + (size_t)NB*NN)

// ---- scratch (static device globals; no allocation) ----
__device__ float g_gates[NB*4*NH];
__device__ float g_h[NB*NH];
__device__ float g_ctrl[NB*NCOUT];
__device__ float g_keys[NB*NKEYS*NM];
__device__ float g_betas[NB*NKEYS];
__device__ float g_knorm[NB*NKEYS];
__device__ float g_free[NB*NR];
__device__ float g_erase[NB*NM];
__device__ float g_wvec[NB*NM];
__device__ float g_agate[NB];
__device__ float g_wgate[NB];
__device__ float g_modes[NB*NR*3];
__device__ float g_taskout[NB*64];
__device__ float g_cw[NB*NKEYS*NN];
__device__ float g_alloc[NB*NN];
__device__ float g_ww[NB*NN];
__device__ float g_fwd[NB*NR*NN];
__device__ float g_bwd[NB*NR*NN];
__device__ float g_reads[NB*NR*NM];

__device__ __forceinline__ float sigm(float x){ return 1.0f/(1.0f+expf(-x)); }
__device__ __forceinline__ float softplusf(float x){ return fmaxf(x,0.0f) + log1pf(expf(-fabsf(x))); }

// ================= K1: LSTM gates =================
__global__ void k_gates(const float* __restrict__ task, const float* __restrict__ prev_reads,
                        const float* __restrict__ h_prev, const float* __restrict__ W_ih,
                        const float* __restrict__ W_hh, const float* __restrict__ b_lstm){
    int gid = blockIdx.x*blockDim.x + threadIdx.x;   // 32768
    int b = gid & (NB-1);
    int g = gid >> 4;
    if (g >= 4*NH) return;
    float acc0 = b_lstm[g], acc1 = 0.0f;
    const float4* wi = (const float4*)(W_ih + (size_t)g*NCIN);
    const float4* t4 = (const float4*)(task + b*64);
    const float4* r4 = (const float4*)(prev_reads + b*(NR*NM));
    #pragma unroll 4
    for (int k = 0; k < 16; k++){
        float4 w = wi[k]; float4 x = t4[k];
        acc0 += w.x*x.x + w.y*x.y; acc1 += w.z*x.z + w.w*x.w;
    }
    #pragma unroll 4
    for (int k = 0; k < 64; k++){
        float4 w = wi[16+k]; float4 x = r4[k];
        acc0 += w.x*x.x + w.y*x.y; acc1 += w.z*x.z + w.w*x.w;
    }
    const float4* wh = (const float4*)(W_hh + (size_t)g*NH);
    const float4* h4 = (const float4*)(h_prev + b*NH);
    #pragma unroll 4
    for (int k = 0; k < 128; k++){
        float4 w = wh[k]; float4 x = h4[k];
        acc0 += w.x*x.x + w.y*x.y; acc1 += w.z*x.z + w.w*x.w;
    }
    g_gates[b*(4*NH) + g] = acc0 + acc1;
}

// ================= K2: LSTM cell =================
__global__ void k_lstm(const float* __restrict__ c_prev){
    int gid = blockIdx.x*blockDim.x + threadIdx.x;   // 8192
    if (gid >= NB*NH) return;
    int b = gid >> 9;
    int k = gid & (NH-1);
    const float* gb = g_gates + b*(4*NH);
    float gi = gb[k], gf = gb[NH+k], gg = gb[2*NH+k], go = gb[3*NH+k];
    float c = sigm(gf)*c_prev[gid] + sigm(gi)*tanhf(gg);
    g_h[gid] = sigm(go)*tanhf(c);
}

// ================= K3: out = h @ W_out^T + b_out =================
__global__ void k_out(const float* __restrict__ W_out, const float* __restrict__ b_out){
    int gid = blockIdx.x*blockDim.x + threadIdx.x;
    if (gid >= NB*NCOUT) return;
    int b = gid & (NB-1);
    int o = gid >> 4;
    float acc0 = b_out[o], acc1 = 0.0f;
    const float4* w4 = (const float4*)(W_out + (size_t)o*NH);
    const float4* h4 = (const float4*)(g_h + b*NH);
    #pragma unroll 4
    for (int k = 0; k < 128; k++){
        float4 w = w4[k]; float4 x = h4[k];
        acc0 += w.x*x.x + w.y*x.y; acc1 += w.z*x.z + w.w*x.w;
    }
    g_ctrl[b*NCOUT + o] = acc0 + acc1;
}

// ================= K3b: parse controller outputs (gridded) =================
__global__ void k_parse1(){
    int idx = blockIdx.x*blockDim.x + threadIdx.x;
    if (idx >= NB*NCOUT) return;
    int b = idx / NCOUT, c = idx % NCOUT;
    float v = g_ctrl[idx];
    if (c < 64)        g_taskout[b*64 + c] = sigm(v);
    else if (c < 320)  g_keys[b*NKEYS*NM + (c-64)] = sigm(v);
    else if (c < 324)  g_betas[b*NKEYS + (c-320)] = 1.0f + softplusf(v);
    else if (c < 328)  g_free[b*NR + (c-324)] = sigm(v);
    else if (c < 392)  g_keys[b*NKEYS*NM + 4*NM + (c-328)] = sigm(v);
    else if (c == 392) g_betas[b*NKEYS + 4] = 1.0f + softplusf(v);
    else if (c < 457)  g_erase[b*NM + (c-393)] = sigm(v);
    else if (c < 521)  g_wvec[b*NM + (c-457)] = sigm(v);
    else if (c == 521) g_agate[b] = sigm(v);
    else if (c == 522) g_wgate[b] = sigm(v);
    else               g_modes[b*12 + (c-523)] = v;
}

__global__ void k_parse2(){
    int tid = threadIdx.x;   // 128
    if (tid < NB*NR){        // read-mode softmax
        float* m = g_modes + tid*3;
        float a = m[0], bb = m[1], cc = m[2];
        float mx = fmaxf(a, fmaxf(bb, cc));
        float e0 = expf(a-mx), e1 = expf(bb-mx), e2 = expf(cc-mx);
        float s = e0+e1+e2;
        m[0]=e0/s; m[1]=e1/s; m[2]=e2/s;
    }
    if (tid < NB*NKEYS){     // key norms
        const float* kp = g_keys + tid*NM;
        float s = 0.0f;
        #pragma unroll 8
        for (int i = 0; i < NM; i++){ float x = kp[i]; s += x*x; }
        g_knorm[tid] = sqrtf(s);
    }
}

// ================= K4: cosine similarity logits (beta*sim) =================
__global__ void k_sim(const float* __restrict__ memory){
    __shared__ float keys_sh[NKEYS*NM];
    __shared__ float beta_sh[NKEYS], kn_sh[NKEYS];
    int b = blockIdx.x >> 5;
    int tile = blockIdx.x & 31;
    int tid = threadIdx.x;
    for (int i = tid; i < NKEYS*NM; i += blockDim.x) keys_sh[i] = g_keys[b*NKEYS*NM + i];
    if (tid < NKEYS){ beta_sh[tid] = g_betas[b*NKEYS+tid]; kn_sh[tid] = g_knorm[b*NKEYS+tid]; }
    __syncthreads();
    int warp = tid >> 5, lane = tid & 31;
    #pragma unroll
    for (int rr = 0; rr < 8; rr++){
        int n = tile*64 + warp*8 + rr;
        const float* mrow = memory + ((size_t)b*NN + n)*NM;
        float a0 = mrow[lane], a1 = mrow[lane+32];
        float nrm = a0*a0 + a1*a1;
        float d0 = a0*keys_sh[0*NM+lane] + a1*keys_sh[0*NM+32+lane];
        float d1 = a0*keys_sh[1*NM+lane] + a1*keys_sh[1*NM+32+lane];
        float d2 = a0*keys_sh[2*NM+lane] + a1*keys_sh[2*NM+32+lane];
        float d3 = a0*keys_sh[3*NM+lane] + a1*keys_sh[3*NM+32+lane];
        float d4 = a0*keys_sh[4*NM+lane] + a1*keys_sh[4*NM+32+lane];
        #pragma unroll
        for (int s = 16; s; s >>= 1){
            nrm += __shfl_xor_sync(0xffffffffu, nrm, s);
            d0  += __shfl_xor_sync(0xffffffffu, d0,  s);
            d1  += __shfl_xor_sync(0xffffffffu, d1,  s);
            d2  += __shfl_xor_sync(0xffffffffu, d2,  s);
            d3  += __shfl_xor_sync(0xffffffffu, d3,  s);
            d4  += __shfl_xor_sync(0xffffffffu, d4,  s);
        }
        if (lane == 0){
            float mn = sqrtf(nrm);
            float dd[5] = {d0,d1,d2,d3,d4};
            #pragma unroll
            for (int k = 0; k < 5; k++)
                g_cw[((size_t)b*NKEYS + k)*NN + n] = beta_sh[k]*dd[k]/(kn_sh[k]*mn + FEPS);
        }
    }
}

// ================= K5: softmax over N per (b,key) row =================
__global__ void k_softmax(){
    __shared__ float buf[NN];
    __shared__ float red[256];
    int row = blockIdx.x;          // 80 rows
    float* p = g_cw + (size_t)row*NN;
    int tid = threadIdx.x;
    float mx = -1e30f;
    for (int i = tid; i < NN; i += 256){ float v = p[i]; buf[i] = v; mx = fmaxf(mx, v); }
    red[tid] = mx; __syncthreads();
    for (int s = 128; s; s >>= 1){ if (tid < s) red[tid] = fmaxf(red[tid], red[tid+s]); __syncthreads(); }
    mx = red[0]; __syncthreads();
    float sum = 0.0f;
    for (int i = tid; i < NN; i += 256){ float e = expf(buf[i]-mx); buf[i] = e; sum += e; }
    red[tid] = sum; __syncthreads();
    for (int s = 128; s; s >>= 1){ if (tid < s) red[tid] += red[tid+s]; __syncthreads(); }
    float inv = 1.0f/red[0];
    for (int i = tid; i < NN; i += 256) p[i] = buf[i]*inv;
}

// ================= K6: usage =================
__global__ void k_usage(const float* __restrict__ pu, const float* __restrict__ pww,
                        const float* __restrict__ prw, float* __restrict__ outU){
    int gid = blockIdx.x*blockDim.x + threadIdx.x;   // 32768
    if (gid >= NB*NN) return;
    int b = gid >> 11;
    int n = gid & (NN-1);
    float psi = 1.0f;
    #pragma unroll
    for (int r = 0; r < NR; r++)
        psi *= 1.0f - g_free[b*NR+r]*prw[((size_t)b*NR + r)*NN + n];
    float u = pu[gid], w = pww[gid];
    outU[gid] = (u + w - u*w)*psi;
}

// ================= K7: allocation weighting =================
__global__ void k_alloc(const float* __restrict__ usage){
    __shared__ float sv[NN];
    __shared__ int   si[NN];
    __shared__ float cA[NN];
    __shared__ float cB[NN];
    int b = blockIdx.x, tid = threadIdx.x;   // 1024 threads
    for (int i = tid; i < NN; i += 1024){ sv[i] = usage[b*NN + i]; si[i] = i; }
    __syncthreads();
    for (int k = 2; k <= NN; k <<= 1){
        for (int j = k >> 1; j > 0; j >>= 1){
            for (int i = tid; i < NN; i += 1024){
                int p = i ^ j;
                if (p > i){
                    float av = sv[i], bv = sv[p];
                    int ai = si[i], bi = si[p];
                    bool gt = (av > bv) || (av == bv && ai > bi);
                    bool up = ((i & k) == 0);
                    if (up == gt){ sv[i]=bv; sv[p]=av; si[i]=bi; si[p]=ai; }
                }
            }
            __syncthreads();
        }
    }
    for (int i = tid; i < NN; i += 1024) cA[i] = sv[i];
    __syncthreads();
    float* src = cA; float* dst = cB;
    for (int off = 1; off < NN; off <<= 1){
        for (int i = tid; i < NN; i += 1024) dst[i] = (i >= off) ? src[i]*src[i-off] : src[i];
        __syncthreads();
        float* t = src; src = dst; dst = t;
    }
    for (int i = tid; i < NN; i += 1024){
        float excl = (i == 0) ? 1.0f : src[i-1];
        g_alloc[b*NN + si[i]] = (1.0f - sv[i])*excl;
    }
}

// ================= K8: write weights + precedence =================
__global__ void k_writew(const float* __restrict__ prec, float* __restrict__ outP){
    __shared__ float red[256];
    int b = blockIdx.x, tid = threadIdx.x;
    float ag = g_agate[b], wg = g_wgate[b];
    const float* cww = g_cw + ((size_t)b*NKEYS + 4)*NN;
    float s = 0.0f;
    for (int n = tid; n < NN; n += 256){
        float ww = wg*(ag*g_alloc[b*NN+n] + (1.0f-ag)*cww[n]);
        g_ww[b*NN+n] = ww;
        s += ww;
    }
    red[tid] = s; __syncthreads();
    for (int st = 128; st; st >>= 1){ if (tid < st) red[tid] += red[tid+st]; __syncthreads(); }
    float oms = 1.0f - red[0];
    for (int n = tid; n < NN; n += 256)
        outP[b*NN+n] = oms*prec[b*NN+n] + g_ww[b*NN+n];
}

// ================= K9: memory erase/write update =================
__global__ void k_memupd(const float* __restrict__ memory, float* __restrict__ outM){
    int t = blockIdx.x*blockDim.x + threadIdx.x;   // 524288 float4s
    if (t >= NB*NN*NM/4) return;
    int m4 = t & 15;
    int n  = (t >> 4) & (NN-1);
    int b  = t >> 15;
    float ww = g_ww[b*NN + n];
    float4 mm = ((const float4*)memory)[t];
    float4 e4 = ((const float4*)g_erase)[b*16 + m4];
    float4 v4 = ((const float4*)g_wvec)[b*16 + m4];
    float4 o;
    o.x = mm.x*(1.0f - ww*e4.x) + ww*v4.x;
    o.y = mm.y*(1.0f - ww*e4.y) + ww*v4.y;
    o.z = mm.z*(1.0f - ww*e4.z) + ww*v4.z;
    o.w = mm.w*(1.0f - ww*e4.w) + ww*v4.w;
    ((float4*)outM)[t] = o;
}

// ================= K10: zero accumulators =================
__global__ void k_zero(){
    int t = blockIdx.x*blockDim.x + threadIdx.x;
    if (t < NB*NR*NN) g_bwd[t] = 0.0f;
    if (t < NB*NR*NM) g_reads[t] = 0.0f;
}

// ================= K11: fused link update + fwd/bwd (float4, one pass over L) ====
// Block = (batch, 32-row tile); 8 warps x 4 rows/warp. Warps sweep columns in
// 8 staggered 256-col phases -> bwd partials in shared without atomics.
__global__ void __launch_bounds__(256, 2)
k_link(const float* __restrict__ L, const float* __restrict__ prw,
       const float* __restrict__ pnew, float* __restrict__ outL){
    extern __shared__ float sm[];
    float* w_sh   = sm;            // 4*2048
    float* bwd_sh = sm + 4*NN;     // 4*2048
    float* p_sh   = sm + 8*NN;     // 2048
    float* wwc_sh = sm + 9*NN;     // 2048
    int b = blockIdx.x >> 6;       // 64 tiles/batch
    int tile = blockIdx.x & 63;
    int rowbase = tile*32;
    int tid = threadIdx.x, warp = tid >> 5, lane = tid & 31;
    for (int i = tid; i < 4*NN; i += 256){ w_sh[i] = prw[(size_t)b*4*NN + i]; bwd_sh[i] = 0.0f; }
    for (int i = tid; i < NN; i += 256){ p_sh[i] = pnew[b*NN + i]; wwc_sh[i] = g_ww[b*NN + i]; }
    __syncthreads();

    int row0 = rowbase + warp*4;
    float wwr[4], wr0[4], wr1[4], wr2[4], wr3[4];
    float f0[4]={0,0,0,0}, f1[4]={0,0,0,0}, f2[4]={0,0,0,0}, f3[4]={0,0,0,0};
    #pragma unroll
    for (int rr = 0; rr < 4; rr++){
        wwr[rr] = wwc_sh[row0+rr];
        wr0[rr] = w_sh[row0+rr];      wr1[rr] = w_sh[NN+row0+rr];
        wr2[rr] = w_sh[2*NN+row0+rr]; wr3[rr] = w_sh[3*NN+row0+rr];
    }
    const float4* L4 = (const float4*)(L + (size_t)b*NN*NN);
    float4* O4 = (float4*)(outL + (size_t)b*NN*NN);
    const float4* w4   = (const float4*)w_sh;
    const float4* p4   = (const float4*)p_sh;
    const float4* wwc4 = (const float4*)wwc_sh;
    float4* bwd4 = (float4*)bwd_sh;

    for (int s = 0; s < 8; s++){
        int chunk = ((warp + s) & 7)*64;   // float4 units; 64 f4 = 256 cols
        #pragma unroll
        for (int c = 0; c < 2; c++){
            int j4 = chunk + c*32 + lane;
            float4 pj = p4[j4];
            float4 wj = wwc4[j4];
            float4 aj = make_float4(1.0f-wj.x, 1.0f-wj.y, 1.0f-wj.z, 1.0f-wj.w);
            float4 k0 = w4[j4], k1 = w4[512+j4], k2 = w4[1024+j4], k3 = w4[1536+j4];
            float4 b0 = make_float4(0,0,0,0), b1 = b0, b2 = b0, b3 = b0;
            #pragma unroll
            for (int rr = 0; rr < 4; rr++){
                size_t off = (size_t)(row0+rr)*(NN/4) + j4;
                float4 l = __ldcs(&L4[off]);
                float arr = wwr[rr];
                float4 o;
                o.x = fmaf(aj.x - arr, l.x, arr*pj.x);
                o.y = fmaf(aj.y - arr, l.y, arr*pj.y);
                o.z = fmaf(aj.z - arr, l.z, arr*pj.z);
                o.w = fmaf(aj.w - arr, l.w, arr*pj.w);
                __stcs(&O4[off], o);
                f0[rr] = fmaf(l.x,k0.x, fmaf(l.y,k0.y, fmaf(l.z,k0.z, fmaf(l.w,k0.w, f0[rr]))));
                f1[rr] = fmaf(l.x,k1.x, fmaf(l.y,k1.y, fmaf(l.z,k1.z, fmaf(l.w,k1.w, f1[rr]))));
                f2[rr] = fmaf(l.x,k2.x, fmaf(l.y,k2.y, fmaf(l.z,k2.z, fmaf(l.w,k2.w, f2[rr]))));
                f3[rr] = fmaf(l.x,k3.x, fmaf(l.y,k3.y, fmaf(l.z,k3.z, fmaf(l.w,k3.w, f3[rr]))));
                b0.x = fmaf(wr0[rr], l.x, b0.x); b0.y = fmaf(wr0[rr], l.y, b0.y);
                b0.z = fmaf(wr0[rr], l.z, b0.z); b0.w = fmaf(wr0[rr], l.w, b0.w);
                b1.x = fmaf(wr1[rr], l.x, b1.x); b1.y = fmaf(wr1[rr], l.y, b1.y);
                b1.z = fmaf(wr1[rr], l.z, b1.z); b1.w = fmaf(wr1[rr], l.w, b1.w);
                b2.x = fmaf(wr2[rr], l.x, b2.x); b2.y = fmaf(wr2[rr], l.y, b2.y);
                b2.z = fmaf(wr2[rr], l.z, b2.z); b2.w = fmaf(wr2[rr], l.w, b2.w);
                b3.x = fmaf(wr3[rr], l.x, b3.x); b3.y = fmaf(wr3[rr], l.y, b3.y);
                b3.z = fmaf(wr3[rr], l.z, b3.z); b3.w = fmaf(wr3[rr], l.w, b3.w);
            }
            float4 t;
            t = bwd4[j4];        t.x+=b0.x; t.y+=b0.y; t.z+=b0.z; t.w+=b0.w; bwd4[j4]        = t;
            t = bwd4[512+j4];    t.x+=b1.x; t.y+=b1.y; t.z+=b1.z; t.w+=b1.w; bwd4[512+j4]    = t;
            t = bwd4[1024+j4];   t.x+=b2.x; t.y+=b2.y; t.z+=b2.z; t.w+=b2.w; bwd4[1024+j4]   = t;
            t = bwd4[1536+j4];   t.x+=b3.x; t.y+=b3.y; t.z+=b3.z; t.w+=b3.w; bwd4[1536+j4]   = t;
        }
        __syncthreads();
    }

    // fwd: warp-reduce and write (block owns these rows exclusively)
    #pragma unroll
    for (int rr = 0; rr < 4; rr++){
        float v0 = f0[rr], v1 = f1[rr], v2 = f2[rr], v3 = f3[rr];
        #pragma unroll
        for (int st = 16; st; st >>= 1){
            v0 += __shfl_xor_sync(0xffffffffu, v0, st);
            v1 += __shfl_xor_sync(0xffffffffu, v1, st);
            v2 += __shfl_xor_sync(0xffffffffu, v2, st);
            v3 += __shfl_xor_sync(0xffffffffu, v3, st);
        }
        if (lane == 0){
            int n = row0 + rr;
            g_fwd[((size_t)b*4 + 0)*NN + n] = v0;
            g_fwd[((size_t)b*4 + 1)*NN + n] = v1;
            g_fwd[((size_t)b*4 + 2)*NN + n] = v2;
            g_fwd[((size_t)b*4 + 3)*NN + n] = v3;
        }
    }
    // diagonal fixup (all stores of this block's rows completed before last barrier)
    if (tid < 32){
        int n = rowbase + tid;
        outL[(size_t)b*NN*NN + (size_t)n*NN + n] = 0.0f;
    }
    // flush bwd partials
    for (int i = tid; i < 4*NN; i += 256)
        atomicAdd(&g_bwd[(size_t)b*4*NN + i], bwd_sh[i]);
}

// ================= K12a: read weights + partial reads (128 blocks) =============
__global__ void k_readw(const float* __restrict__ memory, float* __restrict__ outRW){
    __shared__ float rw_sh[4*256];
    __shared__ float red_sh[NR*NM];   // 256
    __shared__ float modes_sh[12];
    int b = blockIdx.x >> 3;
    int chunk = (blockIdx.x & 7)*256;
    int tid = threadIdx.x;
    if (tid < 12) modes_sh[tid] = g_modes[b*12 + tid];
    red_sh[tid] = 0.0f;
    __syncthreads();
    for (int i = tid; i < 4*256; i += 256){
        int r = i >> 8, nn = i & 255;
        int n = chunk + nn;
        float m0 = modes_sh[r*3+0], m1 = modes_sh[r*3+1], m2 = modes_sh[r*3+2];
        float rw = m0*g_bwd[((size_t)b*4 + r)*NN + n]
                 + m1*g_cw[((size_t)b*NKEYS + r)*NN + n]
                 + m2*g_fwd[((size_t)b*4 + r)*NN + n];
        rw_sh[i] = rw;
        outRW[(size_t)b*4*NN + (size_t)r*NN + n] = rw;
    }
    __syncthreads();
    int warp = tid >> 5, lane = tid & 31;
    float a00=0,a01=0,a10=0,a11=0,a20=0,a21=0,a30=0,a31=0;
    for (int nn = warp; nn < 256; nn += 8){
        int n = chunk + nn;
        const float* mrow = memory + ((size_t)b*NN + n)*NM;
        float v0 = mrow[lane], v1 = mrow[lane+32];
        float r0 = rw_sh[nn], r1 = rw_sh[256+nn], r2 = rw_sh[512+nn], r3 = rw_sh[768+nn];
        a00 = fmaf(r0, v0, a00); a01 = fmaf(r0, v1, a01);
        a10 = fmaf(r1, v0, a10); a11 = fmaf(r1, v1, a11);
        a20 = fmaf(r2, v0, a20); a21 = fmaf(r2, v1, a21);
        a30 = fmaf(r3, v0, a30); a31 = fmaf(r3, v1, a31);
    }
    atomicAdd(&red_sh[0*NM + lane],      a00); atomicAdd(&red_sh[0*NM + lane + 32], a01);
    atomicAdd(&red_sh[1*NM + lane],      a10); atomicAdd(&red_sh[1*NM + lane + 32], a11);
    atomicAdd(&red_sh[2*NM + lane],      a20); atomicAdd(&red_sh[2*NM + lane + 32], a21);
    atomicAdd(&red_sh[3*NM + lane],      a30); atomicAdd(&red_sh[3*NM + lane + 32], a31);
    __syncthreads();
    atomicAdd(&g_reads[b*(NR*NM) + tid], red_sh[tid]);
}

// ================= K12b: read projection + final output (16 blocks) =============
__global__ void k_read2(const float* __restrict__ W_read, const float* __restrict__ b_read,
                        float* __restrict__ outO){
    __shared__ float reads_sh[NR*NM];
    int b = blockIdx.x, tid = threadIdx.x;  // 64 threads
    for (int i = tid; i < NR*NM; i += 64) reads_sh[i] = g_reads[b*(NR*NM) + i];
    __syncthreads();
    float acc = b_read[tid];
    #pragma unroll 8
    for (int k = 0; k < NR*NM; k++)
        acc += W_read[tid*(NR*NM) + k]*reads_sh[k];
    float ro = sigm(acc);
    outO[b*64 + tid] = sigm(ro + g_taskout[b*64 + tid]);
}

// ================= launch =================
extern "C" void kernel_launch(void* const* d_in, const int* in_sizes, int n_in,
                              void* d_out, int out_size){
    const float* task       = (const float*)d_in[0];
    const float* memory     = (const float*)d_in[1];
    const float* L          = (const float*)d_in[2];
    const float* prev_reads = (const float*)d_in[3];
    const float* prw        = (const float*)d_in[4];
    const float* pu         = (const float*)d_in[5];
    const float* pww        = (const float*)d_in[6];
    const float* prec       = (const float*)d_in[7];
    const float* h_prev     = (const float*)d_in[8];
    const float* c_prev     = (const float*)d_in[9];
    const float* W_ih       = (const float*)d_in[10];
    const float* W_hh       = (const float*)d_in[11];
    const float* b_lstm     = (const float*)d_in[12];
    const float* W_out      = (const float*)d_in[13];
    const float* b_out      = (const float*)d_in[14];
    const float* W_read     = (const float*)d_in[15];
    const float* b_read     = (const float*)d_in[16];

    float* out   = (float*)d_out;
    float* outO  = out + OUT_OUTPUT;
    float* outM  = out + OUT_MEM;
    float* outL  = out + OUT_LINK;
    float* outP  = out + OUT_P;
    float* outU  = out + OUT_USAGE;
    float* outRW = out + OUT_READW;

    const int LINK_SMEM = (4*NN + 4*NN + NN + NN) * 4;  // 81920 B
    cudaFuncSetAttribute(k_link, cudaFuncAttributeMaxDynamicSharedMemorySize, LINK_SMEM);

    k_zero   <<<512, 256>>>();
    k_gates  <<<128, 256>>>(task, prev_reads, h_prev, W_ih, W_hh, b_lstm);
    k_lstm   <<<32, 256>>>(c_prev);
    k_out    <<<(NB*NCOUT + 255)/256, 256>>>(W_out, b_out);
    k_parse1 <<<(NB*NCOUT + 255)/256, 256>>>();
    k_parse2 <<<1, 128>>>();
    k_sim    <<<512, 256>>>(memory);
    k_softmax<<<NB*NKEYS, 256>>>();
    k_usage  <<<128, 256>>>(pu, pww, prw, outU);
    k_alloc  <<<NB, 1024>>>(outU);
    k_writew <<<NB, 256>>>(prec, outP);
    k_memupd <<<2048, 256>>>(memory, outM);
    k_link   <<<1024, 256, LINK_SMEM>>>(L, prw, outP, outL);
    k_readw  <<<128, 256>>>(memory, outRW);
    k_read2  <<<NB, 64>>>(W_read, b_read, outO);
}

// round 6
// speedup vs baseline: 1.6461x; 1.5294x over previous
#include <cuda_runtime.h>
#include <math.h>
#include <stdint.h>

#define NB 16
#define NN 2048
#define NM 64
#define NR 4
#define NH 512
#define NCIN 320
#define NCOUT 535
#define NKEYS 5
#define FEPS 1e-8f

// ---- output layout (tuple flattened in reference return order) ----
#define OUT_OUTPUT 0
#define OUT_MEM    ((size_t)(NB*64))
#define OUT_LINK   (OUT_MEM + (size_t)NB*NN*NM)
#define OUT_P      (OUT_LINK + (size_t)NB*NN*NN)
#define OUT_USAGE  (OUT_P + (size_t)NB*NN)
#define OUT_READW  (OUT_USAGE + (size_t)NB*NN)

// ---- scratch (static device globals; no allocation) ----
__device__ float g_gates[NB*4*NH];
__device__ float g_h[NB*NH];
__device__ float g_ctrl[NB*NCOUT];
__device__ float g_keys[NB*NKEYS*NM];
__device__ float g_betas[NB*NKEYS];
__device__ float g_free[NB*NR];
__device__ float g_erase[NB*NM];
__device__ float g_wvec[NB*NM];
__device__ float g_agate[NB];
__device__ float g_wgate[NB];
__device__ float g_modes[NB*NR*3];      // raw logits
__device__ float g_taskout[NB*64];
__device__ float g_cw[NB*NKEYS*NN];
__device__ float g_ww[NB*NN];
__device__ float g_fwd[NB*NR*NN];
__device__ float g_bwd[NB*NR*NN];
__device__ float g_reads[NB*NR*NM];

__device__ __forceinline__ float sigm(float x){ return 1.0f/(1.0f+expf(-x)); }
__device__ __forceinline__ float softplusf(float x){ return fmaxf(x,0.0f) + log1pf(expf(-fabsf(x))); }

// ================= K1: LSTM gates (warp per output) =================
__global__ void k_gates(const float* __restrict__ task, const float* __restrict__ prev_reads,
                        const float* __restrict__ h_prev, const float* __restrict__ W_ih,
                        const float* __restrict__ W_hh, const float* __restrict__ b_lstm){
    int w = (blockIdx.x*blockDim.x + threadIdx.x) >> 5;   // 32768 warps
    int lane = threadIdx.x & 31;
    int b = w & (NB-1);
    int g = w >> 4;             // 0..2047 (= 4*NH)
    float acc = 0.0f;
    const float2* wi = (const float2*)(W_ih + (size_t)g*NCIN);
    const float2* t2 = (const float2*)(task + b*64);
    const float2* r2 = (const float2*)(prev_reads + b*(NR*NM));
    #pragma unroll
    for (int k2 = lane, it = 0; it < 5; k2 += 32, it++){
        float2 wv = wi[k2];
        float2 xv = (k2 < 32) ? t2[k2] : r2[k2-32];
        acc = fmaf(wv.x, xv.x, fmaf(wv.y, xv.y, acc));
    }
    const float2* wh = (const float2*)(W_hh + (size_t)g*NH);
    const float2* h2 = (const float2*)(h_prev + b*NH);
    #pragma unroll
    for (int k2 = lane, it = 0; it < 8; k2 += 32, it++){
        float2 wv = wh[k2], xv = h2[k2];
        acc = fmaf(wv.x, xv.x, fmaf(wv.y, xv.y, acc));
    }
    #pragma unroll
    for (int s = 16; s; s >>= 1) acc += __shfl_xor_sync(0xffffffffu, acc, s);
    if (lane == 0) g_gates[b*(4*NH) + g] = acc + b_lstm[g];
}

// ================= K2: LSTM cell =================
__global__ void k_lstm(const float* __restrict__ c_prev){
    int gid = blockIdx.x*blockDim.x + threadIdx.x;   // 8192
    if (gid >= NB*NH) return;
    int b = gid >> 9;
    int k = gid & (NH-1);
    const float* gb = g_gates + b*(4*NH);
    float gi = gb[k], gf = gb[NH+k], gg = gb[2*NH+k], go = gb[3*NH+k];
    float c = sigm(gf)*c_prev[gid] + sigm(gi)*tanhf(gg);
    g_h[gid] = sigm(go)*tanhf(c);
}

// ================= K3: out = h @ W_out^T + b_out (warp per output) =================
__global__ void k_out(const float* __restrict__ W_out, const float* __restrict__ b_out){
    int w = (blockIdx.x*blockDim.x + threadIdx.x) >> 5;
    if (w >= NB*NCOUT) return;
    int lane = threadIdx.x & 31;
    int b = w & (NB-1);
    int o = w >> 4;
    float acc = 0.0f;
    const float2* w2 = (const float2*)(W_out + (size_t)o*NH);
    const float2* h2 = (const float2*)(g_h + b*NH);
    #pragma unroll
    for (int k2 = lane, it = 0; it < 8; k2 += 32, it++){
        float2 wv = w2[k2], xv = h2[k2];
        acc = fmaf(wv.x, xv.x, fmaf(wv.y, xv.y, acc));
    }
    #pragma unroll
    for (int s = 16; s; s >>= 1) acc += __shfl_xor_sync(0xffffffffu, acc, s);
    if (lane == 0) g_ctrl[b*NCOUT + o] = acc + b_out[o];
}

// ================= K4: parse controller outputs (gridded) =================
__global__ void k_parse(){
    int idx = blockIdx.x*blockDim.x + threadIdx.x;
    if (idx >= NB*NCOUT) return;
    int b = idx / NCOUT, c = idx % NCOUT;
    float v = g_ctrl[idx];
    if (c < 64)        g_taskout[b*64 + c] = sigm(v);
    else if (c < 320)  g_keys[b*NKEYS*NM + (c-64)] = sigm(v);
    else if (c < 324)  g_betas[b*NKEYS + (c-320)] = 1.0f + softplusf(v);
    else if (c < 328)  g_free[b*NR + (c-324)] = sigm(v);
    else if (c < 392)  g_keys[b*NKEYS*NM + 4*NM + (c-328)] = sigm(v);
    else if (c == 392) g_betas[b*NKEYS + 4] = 1.0f + softplusf(v);
    else if (c < 457)  g_erase[b*NM + (c-393)] = sigm(v);
    else if (c < 521)  g_wvec[b*NM + (c-457)] = sigm(v);
    else if (c == 521) g_agate[b] = sigm(v);
    else if (c == 522) g_wgate[b] = sigm(v);
    else               g_modes[b*12 + (c-523)] = v;
}

// ================= K5: cosine similarity logits (beta*sim) =================
__global__ void k_sim(const float* __restrict__ memory){
    __shared__ float keys_sh[NKEYS*NM];
    __shared__ float beta_sh[NKEYS], kn_sh[NKEYS];
    int b = blockIdx.x >> 5;
    int tile = blockIdx.x & 31;
    int tid = threadIdx.x;
    for (int i = tid; i < NKEYS*NM; i += blockDim.x) keys_sh[i] = g_keys[b*NKEYS*NM + i];
    if (tid < NKEYS) beta_sh[tid] = g_betas[b*NKEYS+tid];
    __syncthreads();
    if (tid < NKEYS){
        float s = 0.0f;
        #pragma unroll 8
        for (int i = 0; i < NM; i++){ float x = keys_sh[tid*NM+i]; s += x*x; }
        kn_sh[tid] = sqrtf(s);
    }
    __syncthreads();
    int warp = tid >> 5, lane = tid & 31;
    #pragma unroll
    for (int rr = 0; rr < 8; rr++){
        int n = tile*64 + warp*8 + rr;
        const float* mrow = memory + ((size_t)b*NN + n)*NM;
        float a0 = mrow[lane], a1 = mrow[lane+32];
        float nrm = a0*a0 + a1*a1;
        float d0 = a0*keys_sh[0*NM+lane] + a1*keys_sh[0*NM+32+lane];
        float d1 = a0*keys_sh[1*NM+lane] + a1*keys_sh[1*NM+32+lane];
        float d2 = a0*keys_sh[2*NM+lane] + a1*keys_sh[2*NM+32+lane];
        float d3 = a0*keys_sh[3*NM+lane] + a1*keys_sh[3*NM+32+lane];
        float d4 = a0*keys_sh[4*NM+lane] + a1*keys_sh[4*NM+32+lane];
        #pragma unroll
        for (int s = 16; s; s >>= 1){
            nrm += __shfl_xor_sync(0xffffffffu, nrm, s);
            d0  += __shfl_xor_sync(0xffffffffu, d0,  s);
            d1  += __shfl_xor_sync(0xffffffffu, d1,  s);
            d2  += __shfl_xor_sync(0xffffffffu, d2,  s);
            d3  += __shfl_xor_sync(0xffffffffu, d3,  s);
            d4  += __shfl_xor_sync(0xffffffffu, d4,  s);
        }
        if (lane == 0){
            float mn = sqrtf(nrm);
            float dd[5] = {d0,d1,d2,d3,d4};
            #pragma unroll
            for (int k = 0; k < 5; k++)
                g_cw[((size_t)b*NKEYS + k)*NN + n] = beta_sh[k]*dd[k]/(kn_sh[k]*mn + FEPS);
        }
    }
}

// ================= K6: softmax over N per (b,key) row =================
__global__ void k_softmax(){
    __shared__ float buf[NN];
    __shared__ float red[256];
    int row = blockIdx.x;          // 80 rows
    float* p = g_cw + (size_t)row*NN;
    int tid = threadIdx.x;
    float mx = -1e30f;
    for (int i = tid; i < NN; i += 256){ float v = p[i]; buf[i] = v; mx = fmaxf(mx, v); }
    red[tid] = mx; __syncthreads();
    for (int s = 128; s; s >>= 1){ if (tid < s) red[tid] = fmaxf(red[tid], red[tid+s]); __syncthreads(); }
    mx = red[0]; __syncthreads();
    float sum = 0.0f;
    for (int i = tid; i < NN; i += 256){ float e = expf(buf[i]-mx); buf[i] = e; sum += e; }
    red[tid] = sum; __syncthreads();
    for (int s = 128; s; s >>= 1){ if (tid < s) red[tid] += red[tid+s]; __syncthreads(); }
    float inv = 1.0f/red[0];
    for (int i = tid; i < NN; i += 256) p[i] = buf[i]*inv;
}

// ================= K7: usage + allocation + write weights + precedence ===========
__global__ void k_allocw(const float* __restrict__ pu, const float* __restrict__ pww,
                         const float* __restrict__ prw, const float* __restrict__ prec,
                         float* __restrict__ outU, float* __restrict__ outP){
    __shared__ float sv[NN];
    __shared__ int   si[NN];
    __shared__ float cA[NN];
    __shared__ float cB[NN];
    __shared__ float red[1024];
    int b = blockIdx.x, tid = threadIdx.x;   // 1024 threads
    float fr0 = g_free[b*NR+0], fr1 = g_free[b*NR+1], fr2 = g_free[b*NR+2], fr3 = g_free[b*NR+3];
    for (int i = tid; i < NN; i += 1024){
        float psi = (1.0f - fr0*prw[((size_t)b*NR+0)*NN+i])
                  * (1.0f - fr1*prw[((size_t)b*NR+1)*NN+i])
                  * (1.0f - fr2*prw[((size_t)b*NR+2)*NN+i])
                  * (1.0f - fr3*prw[((size_t)b*NR+3)*NN+i]);
        float u = pu[b*NN+i], w = pww[b*NN+i];
        float usage = (u + w - u*w)*psi;
        outU[b*NN+i] = usage;
        sv[i] = usage; si[i] = i;
    }
    __syncthreads();
    // bitonic ascending, index tie-break == stable argsort
    for (int k = 2; k <= NN; k <<= 1){
        for (int j = k >> 1; j > 0; j >>= 1){
            for (int i = tid; i < NN; i += 1024){
                int p = i ^ j;
                if (p > i){
                    float av = sv[i], bv = sv[p];
                    int ai = si[i], bi = si[p];
                    bool gt = (av > bv) || (av == bv && ai > bi);
                    bool up = ((i & k) == 0);
                    if (up == gt){ sv[i]=bv; sv[p]=av; si[i]=bi; si[p]=ai; }
                }
            }
            __syncthreads();
        }
    }
    for (int i = tid; i < NN; i += 1024) cA[i] = sv[i];
    __syncthreads();
    float* src = cA; float* dst = cB;
    for (int off = 1; off < NN; off <<= 1){
        for (int i = tid; i < NN; i += 1024) dst[i] = (i >= off) ? src[i]*src[i-off] : src[i];
        __syncthreads();
        float* t = src; src = dst; dst = t;
    }
    // scatter alloc -> write weights, accumulate sum
    float ag = g_agate[b], wg = g_wgate[b];
    const float* cww = g_cw + ((size_t)b*NKEYS + 4)*NN;
    float s = 0.0f;
    for (int i = tid; i < NN; i += 1024){
        float excl = (i == 0) ? 1.0f : src[i-1];
        float alloc = (1.0f - sv[i])*excl;
        int n = si[i];
        float ww = wg*(ag*alloc + (1.0f-ag)*cww[n]);
        g_ww[b*NN + n] = ww;
        s += ww;
    }
    red[tid] = s; __syncthreads();
    for (int st = 512; st; st >>= 1){ if (tid < st) red[tid] += red[tid+st]; __syncthreads(); }
    float oms = 1.0f - red[0];
    for (int n = tid; n < NN; n += 1024)
        outP[b*NN+n] = oms*prec[b*NN+n] + g_ww[b*NN+n];
}

// ================= K8: memory erase/write update =================
__global__ void k_memupd(const float* __restrict__ memory, float* __restrict__ outM){
    int t = blockIdx.x*blockDim.x + threadIdx.x;   // 524288 float4s
    if (t >= NB*NN*NM/4) return;
    int m4 = t & 15;
    int n  = (t >> 4) & (NN-1);
    int b  = t >> 15;
    float ww = g_ww[b*NN + n];
    float4 mm = ((const float4*)memory)[t];
    float4 e4 = ((const float4*)g_erase)[b*16 + m4];
    float4 v4 = ((const float4*)g_wvec)[b*16 + m4];
    float4 o;
    o.x = mm.x*(1.0f - ww*e4.x) + ww*v4.x;
    o.y = mm.y*(1.0f - ww*e4.y) + ww*v4.y;
    o.z = mm.z*(1.0f - ww*e4.z) + ww*v4.z;
    o.w = mm.w*(1.0f - ww*e4.w) + ww*v4.w;
    ((float4*)outM)[t] = o;
}

// ================= K9: zero accumulators =================
__global__ void k_zero(){
    int t = blockIdx.x*blockDim.x + threadIdx.x;
    if (t < NB*NR*NN) g_bwd[t] = 0.0f;
    if (t < NB*NR*NM) g_reads[t] = 0.0f;
}

// ================= K10: fused link update + fwd/bwd (float4, batched loads) =====
__global__ void __launch_bounds__(256, 2)
k_link(const float* __restrict__ L, const float* __restrict__ prw,
       const float* __restrict__ pnew, float* __restrict__ outL){
    extern __shared__ float sm[];
    float* w_sh   = sm;            // 4*2048
    float* bwd_sh = sm + 4*NN;     // 4*2048
    float* p_sh   = sm + 8*NN;     // 2048
    float* wwc_sh = sm + 9*NN;     // 2048
    int b = blockIdx.x >> 6;       // 64 tiles/batch
    int tile = blockIdx.x & 63;
    int rowbase = tile*32;
    int tid = threadIdx.x, warp = tid >> 5, lane = tid & 31;
    for (int i = tid; i < 4*NN; i += 256){ w_sh[i] = prw[(size_t)b*4*NN + i]; bwd_sh[i] = 0.0f; }
    for (int i = tid; i < NN; i += 256){ p_sh[i] = pnew[b*NN + i]; wwc_sh[i] = g_ww[b*NN + i]; }
    __syncthreads();

    int row0 = rowbase + warp*4;
    float wwr[4], wr0[4], wr1[4], wr2[4], wr3[4];
    float f0[4]={0,0,0,0}, f1[4]={0,0,0,0}, f2[4]={0,0,0,0}, f3[4]={0,0,0,0};
    #pragma unroll
    for (int rr = 0; rr < 4; rr++){
        wwr[rr] = wwc_sh[row0+rr];
        wr0[rr] = w_sh[row0+rr];      wr1[rr] = w_sh[NN+row0+rr];
        wr2[rr] = w_sh[2*NN+row0+rr]; wr3[rr] = w_sh[3*NN+row0+rr];
    }
    const float4* L4 = (const float4*)(L + (size_t)b*NN*NN);
    float4* O4 = (float4*)(outL + (size_t)b*NN*NN);
    const float4* w4   = (const float4*)w_sh;
    const float4* p4   = (const float4*)p_sh;
    const float4* wwc4 = (const float4*)wwc_sh;
    float4* bwd4 = (float4*)bwd_sh;

    for (int s = 0; s < 8; s++){
        int chunk = ((warp + s) & 7)*64;   // float4 units; 64 f4 = 256 cols
        #pragma unroll
        for (int c = 0; c < 2; c++){
            int j4 = chunk + c*32 + lane;
            // batch all 4 global loads first (MLP=4 guaranteed)
            float4 l[4];
            #pragma unroll
            for (int rr = 0; rr < 4; rr++)
                l[rr] = __ldcs(&L4[(size_t)(row0+rr)*(NN/4) + j4]);
            float4 pj = p4[j4];
            float4 wj = wwc4[j4];
            float4 aj = make_float4(1.0f-wj.x, 1.0f-wj.y, 1.0f-wj.z, 1.0f-wj.w);
            float4 k0 = w4[j4], k1 = w4[512+j4], k2 = w4[1024+j4], k3 = w4[1536+j4];
            float4 b0 = make_float4(0,0,0,0), b1 = b0, b2 = b0, b3 = b0;
            #pragma unroll
            for (int rr = 0; rr < 4; rr++){
                float arr = wwr[rr];
                float4 lv = l[rr];
                float4 o;
                o.x = fmaf(aj.x - arr, lv.x, arr*pj.x);
                o.y = fmaf(aj.y - arr, lv.y, arr*pj.y);
                o.z = fmaf(aj.z - arr, lv.z, arr*pj.z);
                o.w = fmaf(aj.w - arr, lv.w, arr*pj.w);
                __stcs(&O4[(size_t)(row0+rr)*(NN/4) + j4], o);
                f0[rr] = fmaf(lv.x,k0.x, fmaf(lv.y,k0.y, fmaf(lv.z,k0.z, fmaf(lv.w,k0.w, f0[rr]))));
                f1[rr] = fmaf(lv.x,k1.x, fmaf(lv.y,k1.y, fmaf(lv.z,k1.z, fmaf(lv.w,k1.w, f1[rr]))));
                f2[rr] = fmaf(lv.x,k2.x, fmaf(lv.y,k2.y, fmaf(lv.z,k2.z, fmaf(lv.w,k2.w, f2[rr]))));
                f3[rr] = fmaf(lv.x,k3.x, fmaf(lv.y,k3.y, fmaf(lv.z,k3.z, fmaf(lv.w,k3.w, f3[rr]))));
                b0.x = fmaf(wr0[rr], lv.x, b0.x); b0.y = fmaf(wr0[rr], lv.y, b0.y);
                b0.z = fmaf(wr0[rr], lv.z, b0.z); b0.w = fmaf(wr0[rr], lv.w, b0.w);
                b1.x = fmaf(wr1[rr], lv.x, b1.x); b1.y = fmaf(wr1[rr], lv.y, b1.y);
                b1.z = fmaf(wr1[rr], lv.z, b1.z); b1.w = fmaf(wr1[rr], lv.w, b1.w);
                b2.x = fmaf(wr2[rr], lv.x, b2.x); b2.y = fmaf(wr2[rr], lv.y, b2.y);
                b2.z = fmaf(wr2[rr], lv.z, b2.z); b2.w = fmaf(wr2[rr], lv.w, b2.w);
                b3.x = fmaf(wr3[rr], lv.x, b3.x); b3.y = fmaf(wr3[rr], lv.y, b3.y);
                b3.z = fmaf(wr3[rr], lv.z, b3.z); b3.w = fmaf(wr3[rr], lv.w, b3.w);
            }
            float4 t;
            t = bwd4[j4];      t.x+=b0.x; t.y+=b0.y; t.z+=b0.z; t.w+=b0.w; bwd4[j4]      = t;
            t = bwd4[512+j4];  t.x+=b1.x; t.y+=b1.y; t.z+=b1.z; t.w+=b1.w; bwd4[512+j4]  = t;
            t = bwd4[1024+j4]; t.x+=b2.x; t.y+=b2.y; t.z+=b2.z; t.w+=b2.w; bwd4[1024+j4] = t;
            t = bwd4[1536+j4]; t.x+=b3.x; t.y+=b3.y; t.z+=b3.z; t.w+=b3.w; bwd4[1536+j4] = t;
        }
        __syncthreads();
    }

    #pragma unroll
    for (int rr = 0; rr < 4; rr++){
        float v0 = f0[rr], v1 = f1[rr], v2 = f2[rr], v3 = f3[rr];
        #pragma unroll
        for (int st = 16; st; st >>= 1){
            v0 += __shfl_xor_sync(0xffffffffu, v0, st);
            v1 += __shfl_xor_sync(0xffffffffu, v1, st);
            v2 += __shfl_xor_sync(0xffffffffu, v2, st);
            v3 += __shfl_xor_sync(0xffffffffu, v3, st);
        }
        if (lane == 0){
            int n = row0 + rr;
            g_fwd[((size_t)b*4 + 0)*NN + n] = v0;
            g_fwd[((size_t)b*4 + 1)*NN + n] = v1;
            g_fwd[((size_t)b*4 + 2)*NN + n] = v2;
            g_fwd[((size_t)b*4 + 3)*NN + n] = v3;
        }
    }
    // diagonal fixup (all this block's row stores completed before the last barrier)
    if (tid < 32){
        int n = rowbase + tid;
        outL[(size_t)b*NN*NN + (size_t)n*NN + n] = 0.0f;
    }
    for (int i = tid; i < 4*NN; i += 256)
        atomicAdd(&g_bwd[(size_t)b*4*NN + i], bwd_sh[i]);
}

// ================= K11: read weights + partial reads (128 blocks) =============
__global__ void k_readw(const float* __restrict__ memory, float* __restrict__ outRW){
    __shared__ float rw_sh[4*256];
    __shared__ float red_sh[NR*NM];   // 256
    __shared__ float modes_sh[12];
    int b = blockIdx.x >> 3;
    int chunk = (blockIdx.x & 7)*256;
    int tid = threadIdx.x;
    if (tid < NR){
        float a = g_modes[b*12 + tid*3 + 0];
        float bb = g_modes[b*12 + tid*3 + 1];
        float cc = g_modes[b*12 + tid*3 + 2];
        float mx = fmaxf(a, fmaxf(bb, cc));
        float e0 = expf(a-mx), e1 = expf(bb-mx), e2 = expf(cc-mx);
        float s = 1.0f/(e0+e1+e2);
        modes_sh[tid*3+0] = e0*s; modes_sh[tid*3+1] = e1*s; modes_sh[tid*3+2] = e2*s;
    }
    red_sh[tid] = 0.0f;
    __syncthreads();
    for (int i = tid; i < 4*256; i += 256){
        int r = i >> 8, nn = i & 255;
        int n = chunk + nn;
        float m0 = modes_sh[r*3+0], m1 = modes_sh[r*3+1], m2 = modes_sh[r*3+2];
        float rw = m0*g_bwd[((size_t)b*4 + r)*NN + n]
                 + m1*g_cw[((size_t)b*NKEYS + r)*NN + n]
                 + m2*g_fwd[((size_t)b*4 + r)*NN + n];
        rw_sh[i] = rw;
        outRW[(size_t)b*4*NN + (size_t)r*NN + n] = rw;
    }
    __syncthreads();
    int warp = tid >> 5, lane = tid & 31;
    float a00=0,a01=0,a10=0,a11=0,a20=0,a21=0,a30=0,a31=0;
    for (int nn = warp; nn < 256; nn += 8){
        int n = chunk + nn;
        const float* mrow = memory + ((size_t)b*NN + n)*NM;
        float v0 = mrow[lane], v1 = mrow[lane+32];
        float r0 = rw_sh[nn], r1 = rw_sh[256+nn], r2 = rw_sh[512+nn], r3 = rw_sh[768+nn];
        a00 = fmaf(r0, v0, a00); a01 = fmaf(r0, v1, a01);
        a10 = fmaf(r1, v0, a10); a11 = fmaf(r1, v1, a11);
        a20 = fmaf(r2, v0, a20); a21 = fmaf(r2, v1, a21);
        a30 = fmaf(r3, v0, a30); a31 = fmaf(r3, v1, a31);
    }
    atomicAdd(&red_sh[0*NM + lane],      a00); atomicAdd(&red_sh[0*NM + lane + 32], a01);
    atomicAdd(&red_sh[1*NM + lane],      a10); atomicAdd(&red_sh[1*NM + lane + 32], a11);
    atomicAdd(&red_sh[2*NM + lane],      a20); atomicAdd(&red_sh[2*NM + lane + 32], a21);
    atomicAdd(&red_sh[3*NM + lane],      a30); atomicAdd(&red_sh[3*NM + lane + 32], a31);
    __syncthreads();
    atomicAdd(&g_reads[b*(NR*NM) + tid], red_sh[tid]);
}

// ================= K12: read projection + final output (16 blocks) =============
__global__ void k_read2(const float* __restrict__ W_read, const float* __restrict__ b_read,
                        float* __restrict__ outO){
    __shared__ float reads_sh[NR*NM];
    int b = blockIdx.x, tid = threadIdx.x;  // 64 threads
    for (int i = tid; i < NR*NM; i += 64) reads_sh[i] = g_reads[b*(NR*NM) + i];
    __syncthreads();
    float acc = b_read[tid];
    #pragma unroll 8
    for (int k = 0; k < NR*NM; k++)
        acc += W_read[tid*(NR*NM) + k]*reads_sh[k];
    float ro = sigm(acc);
    outO[b*64 + tid] = sigm(ro + g_taskout[b*64 + tid]);
}

// ================= launch =================
extern "C" void kernel_launch(void* const* d_in, const int* in_sizes, int n_in,
                              void* d_out, int out_size){
    const float* task       = (const float*)d_in[0];
    const float* memory     = (const float*)d_in[1];
    const float* L          = (const float*)d_in[2];
    const float* prev_reads = (const float*)d_in[3];
    const float* prw        = (const float*)d_in[4];
    const float* pu         = (const float*)d_in[5];
    const float* pww        = (const float*)d_in[6];
    const float* prec       = (const float*)d_in[7];
    const float* h_prev     = (const float*)d_in[8];
    const float* c_prev     = (const float*)d_in[9];
    const float* W_ih       = (const float*)d_in[10];
    const float* W_hh       = (const float*)d_in[11];
    const float* b_lstm     = (const float*)d_in[12];
    const float* W_out      = (const float*)d_in[13];
    const float* b_out      = (const float*)d_in[14];
    const float* W_read     = (const float*)d_in[15];
    const float* b_read     = (const float*)d_in[16];

    float* out   = (float*)d_out;
    float* outO  = out + OUT_OUTPUT;
    float* outM  = out + OUT_MEM;
    float* outL  = out + OUT_LINK;
    float* outP  = out + OUT_P;
    float* outU  = out + OUT_USAGE;
    float* outRW = out + OUT_READW;

    const int LINK_SMEM = (4*NN + 4*NN + NN + NN) * 4;  // 81920 B
    cudaFuncSetAttribute(k_link, cudaFuncAttributeMaxDynamicSharedMemorySize, LINK_SMEM);

    k_zero   <<<512, 256>>>();
    k_gates  <<<4096, 256>>>(task, prev_reads, h_prev, W_ih, W_hh, b_lstm);
    k_lstm   <<<32, 256>>>(c_prev);
    k_out    <<<(NB*NCOUT*32 + 255)/256, 256>>>(W_out, b_out);
    k_parse  <<<(NB*NCOUT + 255)/256, 256>>>();
    k_sim    <<<512, 256>>>(memory);
    k_softmax<<<NB*NKEYS, 256>>>();
    k_allocw <<<NB, 1024>>>(pu, pww, prw, prec, outU, outP);
    k_memupd <<<2048, 256>>>(memory, outM);
    k_link   <<<1024, 256, LINK_SMEM>>>(L, prw, outP, outL);
    k_readw  <<<128, 256>>>(memory, outRW);
    k_read2  <<<NB, 64>>>(W_read, b_read, outO);
}

// round 7
// speedup vs baseline: 1.7328x; 1.0527x over previous
#include <cuda_runtime.h>
#include <math.h>
#include <stdint.h>

#define NB 16
#define NN 2048
#define NM 64
#define NR 4
#define NH 512
#define NCIN 320
#define NCOUT 535
#define NKEYS 5
#define FEPS 1e-8f
#define NTILE 16          // row tiles per batch in k_link (128 rows each)

// ---- output layout (tuple flattened in reference return order) ----
#define OUT_OUTPUT 0
#define OUT_MEM    ((size_t)(NB*64))
#define OUT_LINK   (OUT_MEM + (size_t)NB*NN*NM)
#define OUT_P      (OUT_LINK + (size_t)NB*NN*NN)
#define OUT_USAGE  (OUT_P + (size_t)NB*NN)
#define OUT_READW  (OUT_USAGE + (size_t)NB*NN)

// ---- scratch (static device globals; no allocation) ----
__device__ float g_gates[NB*4*NH];
__device__ float g_h[NB*NH];
__device__ float g_ctrl[NB*NCOUT];
__device__ float g_keys[NB*NKEYS*NM];
__device__ float g_betas[NB*NKEYS];
__device__ float g_free[NB*NR];
__device__ float g_erase[NB*NM];
__device__ float g_wvec[NB*NM];
__device__ float g_agate[NB];
__device__ float g_wgate[NB];
__device__ float g_modes[NB*NR*3];      // raw logits
__device__ float g_taskout[NB*64];
__device__ float g_cw[NB*NKEYS*NN];
__device__ float g_ww[NB*NN];
__device__ float g_fwd[NB*NR*NN];
__device__ float g_bwdp[(size_t)NTILE*NB*NR*NN];   // per-tile bwd partial slabs (8.4MB)
__device__ float g_reads[NB*NR*NM];

__device__ __forceinline__ float sigm(float x){ return 1.0f/(1.0f+expf(-x)); }
__device__ __forceinline__ float softplusf(float x){ return fmaxf(x,0.0f) + log1pf(expf(-fabsf(x))); }

// ================= K1: LSTM gates (warp per output) =================
__global__ void k_gates(const float* __restrict__ task, const float* __restrict__ prev_reads,
                        const float* __restrict__ h_prev, const float* __restrict__ W_ih,
                        const float* __restrict__ W_hh, const float* __restrict__ b_lstm){
    int w = (blockIdx.x*blockDim.x + threadIdx.x) >> 5;   // 32768 warps
    int lane = threadIdx.x & 31;
    int b = w & (NB-1);
    int g = w >> 4;             // 0..2047 (= 4*NH)
    float acc = 0.0f;
    const float2* wi = (const float2*)(W_ih + (size_t)g*NCIN);
    const float2* t2 = (const float2*)(task + b*64);
    const float2* r2 = (const float2*)(prev_reads + b*(NR*NM));
    #pragma unroll
    for (int k2 = lane, it = 0; it < 5; k2 += 32, it++){
        float2 wv = wi[k2];
        float2 xv = (k2 < 32) ? t2[k2] : r2[k2-32];
        acc = fmaf(wv.x, xv.x, fmaf(wv.y, xv.y, acc));
    }
    const float2* wh = (const float2*)(W_hh + (size_t)g*NH);
    const float2* h2 = (const float2*)(h_prev + b*NH);
    #pragma unroll
    for (int k2 = lane, it = 0; it < 8; k2 += 32, it++){
        float2 wv = wh[k2], xv = h2[k2];
        acc = fmaf(wv.x, xv.x, fmaf(wv.y, xv.y, acc));
    }
    #pragma unroll
    for (int s = 16; s; s >>= 1) acc += __shfl_xor_sync(0xffffffffu, acc, s);
    if (lane == 0) g_gates[b*(4*NH) + g] = acc + b_lstm[g];
}

// ================= K2: LSTM cell =================
__global__ void k_lstm(const float* __restrict__ c_prev){
    int gid = blockIdx.x*blockDim.x + threadIdx.x;   // 8192
    if (gid >= NB*NH) return;
    int b = gid >> 9;
    int k = gid & (NH-1);
    const float* gb = g_gates + b*(4*NH);
    float gi = gb[k], gf = gb[NH+k], gg = gb[2*NH+k], go = gb[3*NH+k];
    float c = sigm(gf)*c_prev[gid] + sigm(gi)*tanhf(gg);
    g_h[gid] = sigm(go)*tanhf(c);
}

// ================= K3: out = h @ W_out^T + b_out (warp per output) =================
__global__ void k_out(const float* __restrict__ W_out, const float* __restrict__ b_out){
    int w = (blockIdx.x*blockDim.x + threadIdx.x) >> 5;
    if (w >= NB*NCOUT) return;
    int lane = threadIdx.x & 31;
    int b = w & (NB-1);
    int o = w >> 4;
    float acc = 0.0f;
    const float2* w2 = (const float2*)(W_out + (size_t)o*NH);
    const float2* h2 = (const float2*)(g_h + b*NH);
    #pragma unroll
    for (int k2 = lane, it = 0; it < 8; k2 += 32, it++){
        float2 wv = w2[k2], xv = h2[k2];
        acc = fmaf(wv.x, xv.x, fmaf(wv.y, xv.y, acc));
    }
    #pragma unroll
    for (int s = 16; s; s >>= 1) acc += __shfl_xor_sync(0xffffffffu, acc, s);
    if (lane == 0) g_ctrl[b*NCOUT + o] = acc + b_out[o];
}

// ================= K4: parse controller outputs + zero g_reads =================
__global__ void k_parse(){
    int idx = blockIdx.x*blockDim.x + threadIdx.x;
    if (idx < NB*NR*NM) g_reads[idx] = 0.0f;
    if (idx >= NB*NCOUT) return;
    int b = idx / NCOUT, c = idx % NCOUT;
    float v = g_ctrl[idx];
    if (c < 64)        g_taskout[b*64 + c] = sigm(v);
    else if (c < 320)  g_keys[b*NKEYS*NM + (c-64)] = sigm(v);
    else if (c < 324)  g_betas[b*NKEYS + (c-320)] = 1.0f + softplusf(v);
    else if (c < 328)  g_free[b*NR + (c-324)] = sigm(v);
    else if (c < 392)  g_keys[b*NKEYS*NM + 4*NM + (c-328)] = sigm(v);
    else if (c == 392) g_betas[b*NKEYS + 4] = 1.0f + softplusf(v);
    else if (c < 457)  g_erase[b*NM + (c-393)] = sigm(v);
    else if (c < 521)  g_wvec[b*NM + (c-457)] = sigm(v);
    else if (c == 521) g_agate[b] = sigm(v);
    else if (c == 522) g_wgate[b] = sigm(v);
    else               g_modes[b*12 + (c-523)] = v;
}

// ================= K5: cosine similarity logits (beta*sim) =================
__global__ void k_sim(const float* __restrict__ memory){
    __shared__ float keys_sh[NKEYS*NM];
    __shared__ float beta_sh[NKEYS], kn_sh[NKEYS];
    int b = blockIdx.x >> 5;
    int tile = blockIdx.x & 31;
    int tid = threadIdx.x;
    for (int i = tid; i < NKEYS*NM; i += blockDim.x) keys_sh[i] = g_keys[b*NKEYS*NM + i];
    if (tid < NKEYS) beta_sh[tid] = g_betas[b*NKEYS+tid];
    __syncthreads();
    if (tid < NKEYS){
        float s = 0.0f;
        #pragma unroll 8
        for (int i = 0; i < NM; i++){ float x = keys_sh[tid*NM+i]; s += x*x; }
        kn_sh[tid] = sqrtf(s);
    }
    __syncthreads();
    int warp = tid >> 5, lane = tid & 31;
    #pragma unroll
    for (int rr = 0; rr < 8; rr++){
        int n = tile*64 + warp*8 + rr;
        const float* mrow = memory + ((size_t)b*NN + n)*NM;
        float a0 = mrow[lane], a1 = mrow[lane+32];
        float nrm = a0*a0 + a1*a1;
        float d0 = a0*keys_sh[0*NM+lane] + a1*keys_sh[0*NM+32+lane];
        float d1 = a0*keys_sh[1*NM+lane] + a1*keys_sh[1*NM+32+lane];
        float d2 = a0*keys_sh[2*NM+lane] + a1*keys_sh[2*NM+32+lane];
        float d3 = a0*keys_sh[3*NM+lane] + a1*keys_sh[3*NM+32+lane];
        float d4 = a0*keys_sh[4*NM+lane] + a1*keys_sh[4*NM+32+lane];
        #pragma unroll
        for (int s = 16; s; s >>= 1){
            nrm += __shfl_xor_sync(0xffffffffu, nrm, s);
            d0  += __shfl_xor_sync(0xffffffffu, d0,  s);
            d1  += __shfl_xor_sync(0xffffffffu, d1,  s);
            d2  += __shfl_xor_sync(0xffffffffu, d2,  s);
            d3  += __shfl_xor_sync(0xffffffffu, d3,  s);
            d4  += __shfl_xor_sync(0xffffffffu, d4,  s);
        }
        if (lane == 0){
            float mn = sqrtf(nrm);
            float dd[5] = {d0,d1,d2,d3,d4};
            #pragma unroll
            for (int k = 0; k < 5; k++)
                g_cw[((size_t)b*NKEYS + k)*NN + n] = beta_sh[k]*dd[k]/(kn_sh[k]*mn + FEPS);
        }
    }
}

// ================= K6: softmax over N per (b,key) row =================
__global__ void k_softmax(){
    __shared__ float buf[NN];
    __shared__ float red[256];
    int row = blockIdx.x;          // 80 rows
    float* p = g_cw + (size_t)row*NN;
    int tid = threadIdx.x;
    float mx = -1e30f;
    for (int i = tid; i < NN; i += 256){ float v = p[i]; buf[i] = v; mx = fmaxf(mx, v); }
    red[tid] = mx; __syncthreads();
    for (int s = 128; s; s >>= 1){ if (tid < s) red[tid] = fmaxf(red[tid], red[tid+s]); __syncthreads(); }
    mx = red[0]; __syncthreads();
    float sum = 0.0f;
    for (int i = tid; i < NN; i += 256){ float e = expf(buf[i]-mx); buf[i] = e; sum += e; }
    red[tid] = sum; __syncthreads();
    for (int s = 128; s; s >>= 1){ if (tid < s) red[tid] += red[tid+s]; __syncthreads(); }
    float inv = 1.0f/red[0];
    for (int i = tid; i < NN; i += 256) p[i] = buf[i]*inv;
}

// ================= K7: usage + allocation + write weights + precedence ===========
__global__ void k_allocw(const float* __restrict__ pu, const float* __restrict__ pww,
                         const float* __restrict__ prw, const float* __restrict__ prec,
                         float* __restrict__ outU, float* __restrict__ outP){
    __shared__ float sv[NN];
    __shared__ int   si[NN];
    __shared__ float cA[NN];
    __shared__ float cB[NN];
    __shared__ float red[1024];
    int b = blockIdx.x, tid = threadIdx.x;   // 1024 threads
    float fr0 = g_free[b*NR+0], fr1 = g_free[b*NR+1], fr2 = g_free[b*NR+2], fr3 = g_free[b*NR+3];
    for (int i = tid; i < NN; i += 1024){
        float psi = (1.0f - fr0*prw[((size_t)b*NR+0)*NN+i])
                  * (1.0f - fr1*prw[((size_t)b*NR+1)*NN+i])
                  * (1.0f - fr2*prw[((size_t)b*NR+2)*NN+i])
                  * (1.0f - fr3*prw[((size_t)b*NR+3)*NN+i]);
        float u = pu[b*NN+i], w = pww[b*NN+i];
        float usage = (u + w - u*w)*psi;
        outU[b*NN+i] = usage;
        sv[i] = usage; si[i] = i;
    }
    __syncthreads();
    for (int k = 2; k <= NN; k <<= 1){
        for (int j = k >> 1; j > 0; j >>= 1){
            for (int i = tid; i < NN; i += 1024){
                int p = i ^ j;
                if (p > i){
                    float av = sv[i], bv = sv[p];
                    int ai = si[i], bi = si[p];
                    bool gt = (av > bv) || (av == bv && ai > bi);
                    bool up = ((i & k) == 0);
                    if (up == gt){ sv[i]=bv; sv[p]=av; si[i]=bi; si[p]=ai; }
                }
            }
            __syncthreads();
        }
    }
    for (int i = tid; i < NN; i += 1024) cA[i] = sv[i];
    __syncthreads();
    float* src = cA; float* dst = cB;
    for (int off = 1; off < NN; off <<= 1){
        for (int i = tid; i < NN; i += 1024) dst[i] = (i >= off) ? src[i]*src[i-off] : src[i];
        __syncthreads();
        float* t = src; src = dst; dst = t;
    }
    float ag = g_agate[b], wg = g_wgate[b];
    const float* cww = g_cw + ((size_t)b*NKEYS + 4)*NN;
    float s = 0.0f;
    for (int i = tid; i < NN; i += 1024){
        float excl = (i == 0) ? 1.0f : src[i-1];
        float alloc = (1.0f - sv[i])*excl;
        int n = si[i];
        float ww = wg*(ag*alloc + (1.0f-ag)*cww[n]);
        g_ww[b*NN + n] = ww;
        s += ww;
    }
    red[tid] = s; __syncthreads();
    for (int st = 512; st; st >>= 1){ if (tid < st) red[tid] += red[tid+st]; __syncthreads(); }
    float oms = 1.0f - red[0];
    for (int n = tid; n < NN; n += 1024)
        outP[b*NN+n] = oms*prec[b*NN+n] + g_ww[b*NN+n];
}

// ================= K8: memory erase/write update =================
__global__ void k_memupd(const float* __restrict__ memory, float* __restrict__ outM){
    int t = blockIdx.x*blockDim.x + threadIdx.x;   // 524288 float4s
    if (t >= NB*NN*NM/4) return;
    int m4 = t & 15;
    int n  = (t >> 4) & (NN-1);
    int b  = t >> 15;
    float ww = g_ww[b*NN + n];
    float4 mm = ((const float4*)memory)[t];
    float4 e4 = ((const float4*)g_erase)[b*16 + m4];
    float4 v4 = ((const float4*)g_wvec)[b*16 + m4];
    float4 o;
    o.x = mm.x*(1.0f - ww*e4.x) + ww*v4.x;
    o.y = mm.y*(1.0f - ww*e4.y) + ww*v4.y;
    o.z = mm.z*(1.0f - ww*e4.z) + ww*v4.z;
    o.w = mm.w*(1.0f - ww*e4.w) + ww*v4.w;
    ((float4*)outM)[t] = o;
}

// ================= K9: fused link update + fwd/bwd — column-ownership =========
// Block = (batch, 128-row tile), 512 threads. Warp owns 128 cols (1 float4/lane).
// bwd accumulates in registers (no barriers, no smem RMW); flushed as a plain
// per-tile partial slab. fwd reduced per-row via shfl + 4-lane shared atomic.
__global__ void __launch_bounds__(512)
k_link(const float* __restrict__ L, const float* __restrict__ prw,
       const float* __restrict__ pnew, float* __restrict__ outL){
    __shared__ float wr_sh[NR][128];
    __shared__ float wwr_sh[128];
    __shared__ float fwd_sh[NR][128];
    int b = blockIdx.x >> 4;
    int tile = blockIdx.x & 15;
    int rowbase = tile*128;
    int tid = threadIdx.x, lane = tid & 31;
    for (int i = tid; i < 128; i += 512){
        wwr_sh[i] = g_ww[b*NN + rowbase + i];
        #pragma unroll
        for (int r = 0; r < NR; r++){
            wr_sh[r][i] = prw[((size_t)b*NR + r)*NN + rowbase + i];
            fwd_sh[r][i] = 0.0f;
        }
    }
    __syncthreads();

    int j4 = tid >> 5;           // wait: need warp*32+lane
    j4 = (tid >> 5)*32 + lane;   // float4 column index 0..511
    float4 pj = ((const float4*)(pnew + (size_t)b*NN))[j4];
    float4 wj = ((const float4*)(g_ww + (size_t)b*NN))[j4];
    float4 aj = make_float4(1.0f-wj.x, 1.0f-wj.y, 1.0f-wj.z, 1.0f-wj.w);
    float4 k0 = ((const float4*)(prw + ((size_t)b*NR+0)*NN))[j4];
    float4 k1 = ((const float4*)(prw + ((size_t)b*NR+1)*NN))[j4];
    float4 k2 = ((const float4*)(prw + ((size_t)b*NR+2)*NN))[j4];
    float4 k3 = ((const float4*)(prw + ((size_t)b*NR+3)*NN))[j4];
    float4 bw0 = make_float4(0,0,0,0), bw1 = bw0, bw2 = bw0, bw3 = bw0;
    const float4* L4 = (const float4*)(L + (size_t)b*NN*NN) + j4;
    float4* O4 = (float4*)(outL + (size_t)b*NN*NN) + j4;
    int c0 = j4 << 2;

    float4 l = __ldcs(&L4[(size_t)rowbase*(NN/4)]);
    for (int r = 0; r < 128; r++){
        int row = rowbase + r;
        float4 lv = l;
        if (r < 127) l = __ldcs(&L4[(size_t)(row+1)*(NN/4)]);
        float arr = wwr_sh[r];
        float4 o;
        o.x = fmaf(aj.x - arr, lv.x, arr*pj.x);
        o.y = fmaf(aj.y - arr, lv.y, arr*pj.y);
        o.z = fmaf(aj.z - arr, lv.z, arr*pj.z);
        o.w = fmaf(aj.w - arr, lv.w, arr*pj.w);
        int d = row - c0;
        if ((unsigned)d < 4u){
            if (d == 0) o.x = 0.0f; else if (d == 1) o.y = 0.0f;
            else if (d == 2) o.z = 0.0f; else o.w = 0.0f;
        }
        __stcs(&O4[(size_t)row*(NN/4)], o);
        // fwd partials (scalar per key, reduce over warp now)
        float f0 = lv.x*k0.x + lv.y*k0.y + lv.z*k0.z + lv.w*k0.w;
        float f1 = lv.x*k1.x + lv.y*k1.y + lv.z*k1.z + lv.w*k1.w;
        float f2 = lv.x*k2.x + lv.y*k2.y + lv.z*k2.z + lv.w*k2.w;
        float f3 = lv.x*k3.x + lv.y*k3.y + lv.z*k3.z + lv.w*k3.w;
        #pragma unroll
        for (int s = 16; s; s >>= 1){
            f0 += __shfl_xor_sync(0xffffffffu, f0, s);
            f1 += __shfl_xor_sync(0xffffffffu, f1, s);
            f2 += __shfl_xor_sync(0xffffffffu, f2, s);
            f3 += __shfl_xor_sync(0xffffffffu, f3, s);
        }
        if (lane < 4){
            float fv = (lane == 0) ? f0 : (lane == 1) ? f1 : (lane == 2) ? f2 : f3;
            atomicAdd(&fwd_sh[lane][r], fv);
        }
        // bwd register accumulation
        float w0 = wr_sh[0][r], w1 = wr_sh[1][r], w2 = wr_sh[2][r], w3 = wr_sh[3][r];
        bw0.x = fmaf(w0, lv.x, bw0.x); bw0.y = fmaf(w0, lv.y, bw0.y);
        bw0.z = fmaf(w0, lv.z, bw0.z); bw0.w = fmaf(w0, lv.w, bw0.w);
        bw1.x = fmaf(w1, lv.x, bw1.x); bw1.y = fmaf(w1, lv.y, bw1.y);
        bw1.z = fmaf(w1, lv.z, bw1.z); bw1.w = fmaf(w1, lv.w, bw1.w);
        bw2.x = fmaf(w2, lv.x, bw2.x); bw2.y = fmaf(w2, lv.y, bw2.y);
        bw2.z = fmaf(w2, lv.z, bw2.z); bw2.w = fmaf(w2, lv.w, bw2.w);
        bw3.x = fmaf(w3, lv.x, bw3.x); bw3.y = fmaf(w3, lv.y, bw3.y);
        bw3.z = fmaf(w3, lv.z, bw3.z); bw3.w = fmaf(w3, lv.w, bw3.w);
    }

    // bwd partial slab: plain coalesced stores (block owns all 2048 cols once)
    float4* slab = (float4*)(g_bwdp + (((size_t)tile*NB + b)*NR)*NN);
    slab[0*(NN/4) + j4] = bw0;
    slab[1*(NN/4) + j4] = bw1;
    slab[2*(NN/4) + j4] = bw2;
    slab[3*(NN/4) + j4] = bw3;

    __syncthreads();
    // fwd: rows exclusive to this block
    for (int i = tid; i < NR*128; i += 512){
        int r = i >> 7, rr = i & 127;
        g_fwd[((size_t)b*NR + r)*NN + rowbase + rr] = fwd_sh[r][rr];
    }
}

// ================= K10: read weights + partial reads (128 blocks) =============
__global__ void k_readw(const float* __restrict__ memory, float* __restrict__ outRW){
    __shared__ float rw_sh[4*256];
    __shared__ float red_sh[NR*NM];   // 256
    __shared__ float modes_sh[12];
    int b = blockIdx.x >> 3;
    int chunk = (blockIdx.x & 7)*256;
    int tid = threadIdx.x;
    if (tid < NR){
        float a = g_modes[b*12 + tid*3 + 0];
        float bb = g_modes[b*12 + tid*3 + 1];
        float cc = g_modes[b*12 + tid*3 + 2];
        float mx = fmaxf(a, fmaxf(bb, cc));
        float e0 = expf(a-mx), e1 = expf(bb-mx), e2 = expf(cc-mx);
        float s = 1.0f/(e0+e1+e2);
        modes_sh[tid*3+0] = e0*s; modes_sh[tid*3+1] = e1*s; modes_sh[tid*3+2] = e2*s;
    }
    red_sh[tid] = 0.0f;
    __syncthreads();
    for (int i = tid; i < 4*256; i += 256){
        int r = i >> 8, nn = i & 255;
        int n = chunk + nn;
        // sum bwd partial slabs over 16 tiles
        float bsum = 0.0f;
        #pragma unroll
        for (int t = 0; t < NTILE; t++)
            bsum += g_bwdp[(((size_t)t*NB + b)*NR + r)*NN + n];
        float m0 = modes_sh[r*3+0], m1 = modes_sh[r*3+1], m2 = modes_sh[r*3+2];
        float rw = m0*bsum
                 + m1*g_cw[((size_t)b*NKEYS + r)*NN + n]
                 + m2*g_fwd[((size_t)b*NR + r)*NN + n];
        rw_sh[i] = rw;
        outRW[(size_t)b*NR*NN + (size_t)r*NN + n] = rw;
    }
    __syncthreads();
    int warp = tid >> 5, lane = tid & 31;
    float a00=0,a01=0,a10=0,a11=0,a20=0,a21=0,a30=0,a31=0;
    for (int nn = warp; nn < 256; nn += 8){
        int n = chunk + nn;
        const float* mrow = memory + ((size_t)b*NN + n)*NM;
        float v0 = mrow[lane], v1 = mrow[lane+32];
        float r0 = rw_sh[nn], r1 = rw_sh[256+nn], r2 = rw_sh[512+nn], r3 = rw_sh[768+nn];
        a00 = fmaf(r0, v0, a00); a01 = fmaf(r0, v1, a01);
        a10 = fmaf(r1, v0, a10); a11 = fmaf(r1, v1, a11);
        a20 = fmaf(r2, v0, a20); a21 = fmaf(r2, v1, a21);
        a30 = fmaf(r3, v0, a30); a31 = fmaf(r3, v1, a31);
    }
    atomicAdd(&red_sh[0*NM + lane],      a00); atomicAdd(&red_sh[0*NM + lane + 32], a01);
    atomicAdd(&red_sh[1*NM + lane],      a10); atomicAdd(&red_sh[1*NM + lane + 32], a11);
    atomicAdd(&red_sh[2*NM + lane],      a20); atomicAdd(&red_sh[2*NM + lane + 32], a21);
    atomicAdd(&red_sh[3*NM + lane],      a30); atomicAdd(&red_sh[3*NM + lane + 32], a31);
    __syncthreads();
    atomicAdd(&g_reads[b*(NR*NM) + tid], red_sh[tid]);
}

// ================= K11: read projection + final output (16 blocks) =============
__global__ void k_read2(const float* __restrict__ W_read, const float* __restrict__ b_read,
                        float* __restrict__ outO){
    __shared__ float reads_sh[NR*NM];
    int b = blockIdx.x, tid = threadIdx.x;  // 64 threads
    for (int i = tid; i < NR*NM; i += 64) reads_sh[i] = g_reads[b*(NR*NM) + i];
    __syncthreads();
    float acc = b_read[tid];
    #pragma unroll 8
    for (int k = 0; k < NR*NM; k++)
        acc += W_read[tid*(NR*NM) + k]*reads_sh[k];
    float ro = sigm(acc);
    outO[b*64 + tid] = sigm(ro + g_taskout[b*64 + tid]);
}

// ================= launch =================
extern "C" void kernel_launch(void* const* d_in, const int* in_sizes, int n_in,
                              void* d_out, int out_size){
    const float* task       = (const float*)d_in[0];
    const float* memory     = (const float*)d_in[1];
    const float* L          = (const float*)d_in[2];
    const float* prev_reads = (const float*)d_in[3];
    const float* prw        = (const float*)d_in[4];
    const float* pu         = (const float*)d_in[5];
    const float* pww        = (const float*)d_in[6];
    const float* prec       = (const float*)d_in[7];
    const float* h_prev     = (const float*)d_in[8];
    const float* c_prev     = (const float*)d_in[9];
    const float* W_ih       = (const float*)d_in[10];
    const float* W_hh       = (const float*)d_in[11];
    const float* b_lstm     = (const float*)d_in[12];
    const float* W_out      = (const float*)d_in[13];
    const float* b_out      = (const float*)d_in[14];
    const float* W_read     = (const float*)d_in[15];
    const float* b_read     = (const float*)d_in[16];

    float* out   = (float*)d_out;
    float* outO  = out + OUT_OUTPUT;
    float* outM  = out + OUT_MEM;
    float* outL  = out + OUT_LINK;
    float* outP  = out + OUT_P;
    float* outU  = out + OUT_USAGE;
    float* outRW = out + OUT_READW;

    k_gates  <<<4096, 256>>>(task, prev_reads, h_prev, W_ih, W_hh, b_lstm);
    k_lstm   <<<32, 256>>>(c_prev);
    k_out    <<<(NB*NCOUT*32 + 255)/256, 256>>>(W_out, b_out);
    k_parse  <<<(NB*NCOUT + 255)/256, 256>>>();
    k_sim    <<<512, 256>>>(memory);
    k_softmax<<<NB*NKEYS, 256>>>();
    k_allocw <<<NB, 1024>>>(pu, pww, prw, prec, outU, outP);
    k_memupd <<<2048, 256>>>(memory, outM);
    k_link   <<<NB*NTILE, 512>>>(L, prw, outP, outL);
    k_readw  <<<128, 256>>>(memory, outRW);
    k_read2  <<<NB, 64>>>(W_read, b_read, outO);
}